// round 11
// baseline (speedup 1.0000x reference)
#include <cuda_runtime.h>
#include <cuda_bf16.h>
#include <cstdint>

#define SEQ   512
#define BATCH 64
#define FEAT  512
#define COMP  256
#define NHEAD 8

// Scratch (allocation-free rule: __device__ globals)
__device__ uint32_t g_d3p[(size_t)SEQ * BATCH * 256];   // d3 bf16 split: [row][128 hi | 128 lo] words
__device__ float g_tv[(size_t)BATCH * SEQ * COMP];      // [64][512][256]
__device__ float g_d4[BATCH * COMP];                    // [64][256]
__device__ float g_y2[NHEAD * BATCH * COMP];            // [8][64][256]
__device__ float g_attsp[2 * NHEAD * BATCH * SEQ];      // two c-half partials
__device__ float g_scores[NHEAD * BATCH * SEQ];
__device__ float g_vsp[8 * BATCH * NHEAD * COMP];       // [8 sb][64][2048]
// W^T bf16 split for k_att: [h][c][k<256]
__device__ __align__(16) __nv_bfloat16 g_Wth[NHEAD * 256 * 256];
__device__ __align__(16) __nv_bfloat16 g_Wtl[NHEAD * 256 * 256];
// w1/wv transposed split for k_proj: [path][c][k<512]
__device__ __align__(16) __nv_bfloat16 g_wpth[2 * 256 * 512];
__device__ __align__(16) __nv_bfloat16 g_wptl[2 * 256 * 512];

__device__ __forceinline__ uint32_t smem_u32(const void* p) {
    uint32_t a;
    asm("{ .reg .u64 t; cvta.to.shared.u64 t, %1; cvt.u32.u64 %0, t; }" : "=r"(a) : "l"(p));
    return a;
}

#define CP16(dst, src) \
    asm volatile("cp.async.ca.shared.global [%0], [%1], 16;" :: "r"(dst), "l"(src) : "memory")
#define CP_COMMIT() asm volatile("cp.async.commit_group;" ::: "memory")
#define CP_WAIT(n)  asm volatile("cp.async.wait_group %0;" :: "n"(n) : "memory")

// bf16 split of a pair of floats -> packed hi and lo words
__device__ __forceinline__ void split2(float a, float b, uint32_t& hi, uint32_t& lo) {
    __nv_bfloat16 ha = __float2bfloat16_rn(a);
    __nv_bfloat16 hb = __float2bfloat16_rn(b);
    __nv_bfloat16 la = __float2bfloat16_rn(a - __bfloat162float(ha));
    __nv_bfloat16 lb = __float2bfloat16_rn(b - __bfloat162float(hb));
    hi = (uint32_t)__bfloat16_as_ushort(ha) | ((uint32_t)__bfloat16_as_ushort(hb) << 16);
    lo = (uint32_t)__bfloat16_as_ushort(la) | ((uint32_t)__bfloat16_as_ushort(lb) << 16);
}

__device__ __forceinline__ void mma16816(float c[4], const uint32_t a[4],
                                         uint32_t b0, uint32_t b1) {
    asm volatile(
        "mma.sync.aligned.m16n8k16.row.col.f32.bf16.bf16.f32 "
        "{%0,%1,%2,%3}, {%4,%5,%6,%7}, {%8,%9}, {%0,%1,%2,%3};"
        : "+f"(c[0]), "+f"(c[1]), "+f"(c[2]), "+f"(c[3])
        : "r"(a[0]), "r"(a[1]), "r"(a[2]), "r"(a[3]), "r"(b0), "r"(b1));
}

__device__ __forceinline__ void ldsm_x4(uint32_t r[4], uint32_t addr) {
    asm volatile("ldmatrix.sync.aligned.m8n8.x4.shared.b16 {%0,%1,%2,%3}, [%4];"
        : "=r"(r[0]), "=r"(r[1]), "=r"(r[2]), "=r"(r[3]) : "r"(addr));
}

// ===========================================================================
// d4 = relu(d1 @ w1 + b1)   [64,256]
// ===========================================================================
__global__ void k_d4(const float* __restrict__ d1, const float* __restrict__ w1,
                     const float* __restrict__ b1) {
    __shared__ float row[FEAT];
    int b = blockIdx.x, c = threadIdx.x;
    for (int i = c; i < FEAT; i += blockDim.x) row[i] = d1[b * FEAT + i];
    __syncthreads();
    float acc = b1[c];
#pragma unroll 8
    for (int d = 0; d < FEAT; d++) acc = fmaf(row[d], w1[d * COMP + c], acc);
    g_d4[b * COMP + c] = fmaxf(acc, 0.f);
}

// ===========================================================================
// 64-row fp32 tile GEMM (round-2 proven). 256 threads, 8x8 microtile.
// ===========================================================================
template <int K, int LDA>
__device__ __forceinline__ void gemm_tile64(const float* __restrict__ A,
                                            const float* __restrict__ Bm,
                                            float acc[8][8]) {
    __shared__ float As[16 * 64];
    __shared__ float Bs[16 * 256];
    int tid  = threadIdx.x;
    int am   = tid >> 2;
    int ak   = (tid & 3) << 2;
    int bn   = (tid & 63) << 2;
    int bk   = (tid >> 6) << 2;
    int rowb = (tid >> 5) << 3;
    int cb   = (tid & 31) << 2;

#pragma unroll
    for (int i = 0; i < 8; i++)
#pragma unroll
        for (int j = 0; j < 8; j++) acc[i][j] = 0.f;

    for (int k0 = 0; k0 < K; k0 += 16) {
        float4 av = *(const float4*)(A + am * LDA + k0 + ak);
        As[(ak + 0) * 64 + am] = av.x;
        As[(ak + 1) * 64 + am] = av.y;
        As[(ak + 2) * 64 + am] = av.z;
        As[(ak + 3) * 64 + am] = av.w;
#pragma unroll
        for (int i = 0; i < 4; i++) {
            *(float4*)(Bs + (bk + i) * 256 + bn) =
                *(const float4*)(Bm + (size_t)(k0 + bk + i) * 256 + bn);
        }
        __syncthreads();
#pragma unroll
        for (int kk = 0; kk < 16; kk++) {
            float4 a0 = *(const float4*)(As + kk * 64 + rowb);
            float4 a1 = *(const float4*)(As + kk * 64 + rowb + 4);
            float4 b0 = *(const float4*)(Bs + kk * 256 + cb);
            float4 b1 = *(const float4*)(Bs + kk * 256 + cb + 128);
            float a[8]  = {a0.x, a0.y, a0.z, a0.w, a1.x, a1.y, a1.z, a1.w};
            float bb[8] = {b0.x, b0.y, b0.z, b0.w, b1.x, b1.y, b1.z, b1.w};
#pragma unroll
            for (int i = 0; i < 8; i++)
#pragma unroll
                for (int j = 0; j < 8; j++)
                    acc[i][j] = fmaf(a[i], bb[j], acc[i][j]);
        }
        __syncthreads();
    }
}

// ===========================================================================
// y2[h][b][c] = d4[b,:] @ W_h[256:512,:]   grid NHEAD, block 256.
// ===========================================================================
__global__ void __launch_bounds__(256)
k_y2(const float* __restrict__ W) {
    int h = blockIdx.x;
    float acc[8][8];
    gemm_tile64<COMP, COMP>(g_d4, W + (size_t)h * 512 * 256 + 256 * 256, acc);
    int tid  = threadIdx.x;
    int rowb = (tid >> 5) << 3;
    int cb   = (tid & 31) << 2;
#pragma unroll
    for (int i = 0; i < 8; i++)
#pragma unroll
        for (int j = 0; j < 8; j++) {
            int c = (j < 4) ? cb + j : cb + 124 + j;
            g_y2[((size_t)h * 64 + rowb + i) * 256 + c] = acc[i][j];
        }
}

// ===========================================================================
// Weight split prep (fused): blocks 0..7 -> W^T split (k_att);
// blocks 8..9 -> w1/wv transposed split (k_proj). grid 10, block 256.
// ===========================================================================
__global__ void __launch_bounds__(256)
k_wsplit(const float* __restrict__ W, const float* __restrict__ w1,
         const float* __restrict__ wv) {
    if (blockIdx.x < 8) {
        int h = blockIdx.x;
        for (int i = threadIdx.x; i < 256 * 256; i += 256) {
            int k = i >> 8, c = i & 255;
            float v = W[((size_t)h * 512 + k) * 256 + c];
            __nv_bfloat16 hi = __float2bfloat16_rn(v);
            __nv_bfloat16 lo = __float2bfloat16_rn(v - __bfloat162float(hi));
            size_t o = ((size_t)h * 256 + c) * 256 + k;
            g_Wth[o] = hi;
            g_Wtl[o] = lo;
        }
    } else {
        int path = blockIdx.x - 8;
        const float* w = path ? wv : w1;
        for (int i = threadIdx.x; i < 256 * 512; i += 256) {
            int c = i >> 9, k = i & 511;
            float v = w[(size_t)k * 256 + c];
            __nv_bfloat16 hi = __float2bfloat16_rn(v);
            __nv_bfloat16 lo = __float2bfloat16_rn(v - __bfloat162float(hi));
            size_t o = ((size_t)path * 256 + c) * 512 + k;
            g_wpth[o] = hi;
            g_wptl[o] = lo;
        }
    }
}

// ===========================================================================
// k_proj via HMMA bf16-split + ldmatrix, 32x64 warp tile.
// grid (2 cx, 2 path, 256 mblk), blk 256. Warps: 4m x 2n over 128x128 tile.
// Smem words: Ah 0, Al 4608, Bh 9216, Bl 13824 (pitch 36), b1s 18432.
// ===========================================================================
#define PROJ_SMEM_WORDS 18560
#define PROJ_SMEM_BYTES (PROJ_SMEM_WORDS * 4)

__global__ void __launch_bounds__(256, 2)
k_proj_mma(const float* __restrict__ d2, const float* __restrict__ b1) {
    extern __shared__ __align__(16) uint32_t sm[];
    uint32_t* Ah = sm;
    uint32_t* Al = sm + 4608;
    uint32_t* Bh = sm + 9216;
    uint32_t* Bl = sm + 13824;
    float*    b1s = (float*)(sm + 18432);

    const int cx = blockIdx.x, path = blockIdx.y, zb = blockIdx.z;
    const int m0 = zb * 128;
    const int tid = threadIdx.x;
    const int wid = tid >> 5;
    const int lane = tid & 31;
    const int g  = lane >> 2;
    const int tg = lane & 3;
    const int wm = wid & 3, wn = wid >> 2;

    if (path == 0 && tid < 128) b1s[tid] = b1[cx * 128 + tid];

    const uint32_t smb = smem_u32(sm);
    uint32_t aaddr_h[2], aaddr_l[2];
#pragma unroll
    for (int mt = 0; mt < 2; mt++) {
        int r = wm * 32 + mt * 16 + (lane & 7) + ((lane >> 3) & 1) * 8;
        aaddr_h[mt] = smb + (uint32_t)(r * 36 + (lane >> 4) * 4) * 4;
        aaddr_l[mt] = aaddr_h[mt] + 4608u * 4;
    }
    uint32_t baddr_h[4], baddr_l[4];
#pragma unroll
    for (int bn = 0; bn < 4; bn++) {
        int r = wn * 64 + bn * 16 + (lane & 7) + ((lane >> 4) << 3);
        baddr_h[bn] = smb + (uint32_t)(9216 + r * 36 + ((lane >> 3) & 1) * 4) * 4;
        baddr_l[bn] = baddr_h[bn] + 4608u * 4;
    }

    float acc[2][8][4];
#pragma unroll
    for (int mt = 0; mt < 2; mt++)
#pragma unroll
        for (int j = 0; j < 8; j++)
#pragma unroll
            for (int e = 0; e < 4; e++) acc[mt][j][e] = 0.f;

    const __nv_bfloat16* Wh = g_wpth + ((size_t)path * 256 + cx * 128) * 512;
    const __nv_bfloat16* Wl = g_wptl + ((size_t)path * 256 + cx * 128) * 512;

    for (int ch = 0; ch < 8; ch++) {
        __syncthreads();
        // A chunk: fp32 -> bf16 hi/lo split inline (128 rows x 64 k)
        for (int t = tid; t < 2048; t += 256) {
            int r = t >> 4, j = t & 15;
            float4 v = *(const float4*)(d2 + (size_t)(m0 + r) * 512 + ch * 64 + j * 4);
            uint32_t hi0, lo0, hi1, lo1;
            split2(v.x, v.y, hi0, lo0);
            split2(v.z, v.w, hi1, lo1);
            Ah[r * 36 + j * 2]     = hi0;
            Ah[r * 36 + j * 2 + 1] = hi1;
            Al[r * 36 + j * 2]     = lo0;
            Al[r * 36 + j * 2 + 1] = lo1;
        }
        for (int t = tid; t < 2048; t += 256) {
            int n = t >> 4, j = t & 15;
            int plane = j >> 3, j8 = j & 7;
            const uint4* srow = (const uint4*)((plane ? Wl : Wh) + (size_t)n * 512 + ch * 64);
            uint32_t* dstp = (plane ? Bl : Bh) + n * 36 + j8 * 4;
            *(uint4*)dstp = srow[j8];
        }
        __syncthreads();

#pragma unroll
        for (int ks = 0; ks < 4; ks++) {
            const uint32_t kb = (uint32_t)(ks * 8) * 4;
            uint32_t ah[2][4], al[2][4];
            ldsm_x4(ah[0], aaddr_h[0] + kb);
            ldsm_x4(ah[1], aaddr_h[1] + kb);
            ldsm_x4(al[0], aaddr_l[0] + kb);
            ldsm_x4(al[1], aaddr_l[1] + kb);
#pragma unroll
            for (int bn = 0; bn < 4; bn++) {
                uint32_t bh[4], bl[4];
                ldsm_x4(bh, baddr_h[bn] + kb);
                ldsm_x4(bl, baddr_l[bn] + kb);
#pragma unroll
                for (int mt = 0; mt < 2; mt++) {
                    mma16816(acc[mt][2 * bn],     ah[mt], bh[0], bh[1]);
                    mma16816(acc[mt][2 * bn],     ah[mt], bl[0], bl[1]);
                    mma16816(acc[mt][2 * bn],     al[mt], bh[0], bh[1]);
                    mma16816(acc[mt][2 * bn + 1], ah[mt], bh[2], bh[3]);
                    mma16816(acc[mt][2 * bn + 1], ah[mt], bl[2], bl[3]);
                    mma16816(acc[mt][2 * bn + 1], al[mt], bh[2], bh[3]);
                }
            }
        }
    }

#pragma unroll
    for (int mt = 0; mt < 2; mt++) {
        const int R0 = m0 + wm * 32 + mt * 16 + g;
        const int R1 = R0 + 8;
        if (path == 0) {
            uint32_t* dst0 = g_d3p + (size_t)R0 * 256;
            uint32_t* dst1 = g_d3p + (size_t)R1 * 256;
#pragma unroll
            for (int j = 0; j < 8; j++) {
                const int ch_ = wn * 64 + j * 8 + tg * 2;      // col within cx half
                const int word = cx * 64 + wn * 32 + j * 4 + tg;
                const float bb0 = b1s[ch_], bb1 = b1s[ch_ + 1];
                uint32_t hi, lo;
                float v0 = fmaxf(acc[mt][j][0] + bb0, 0.f);
                float v1 = fmaxf(acc[mt][j][1] + bb1, 0.f);
                split2(v0, v1, hi, lo);
                dst0[word] = hi; dst0[128 + word] = lo;
                float v2 = fmaxf(acc[mt][j][2] + bb0, 0.f);
                float v3 = fmaxf(acc[mt][j][3] + bb1, 0.f);
                split2(v2, v3, hi, lo);
                dst1[word] = hi; dst1[128 + word] = lo;
            }
        } else {
            const int s0 = R0 >> 6, b0i = R0 & 63;
            const int s1 = R1 >> 6, b1i = R1 & 63;
            float* t0 = g_tv + ((size_t)b0i * 512 + s0) * 256 + cx * 128;
            float* t1 = g_tv + ((size_t)b1i * 512 + s1) * 256 + cx * 128;
#pragma unroll
            for (int j = 0; j < 8; j++) {
                const int cc = wn * 64 + j * 8 + tg * 2;
                *(float2*)(t0 + cc) = make_float2(tanhf(acc[mt][j][0]), tanhf(acc[mt][j][1]));
                *(float2*)(t1 + cc) = make_float2(tanhf(acc[mt][j][2]), tanhf(acc[mt][j][3]));
            }
        }
    }
}

// ===========================================================================
// k_att via HMMA + cp.async 2-stage pipeline, 32x64 warp tile.
// grid (2 cx, 8 h, 256), blk 256. k=32 chunks (8), double-buffered.
// Buf layout (words, pitch 20): Ah [0,2560) Al [2560,5120) Bh [5120,7680)
// Bl [7680,10240); buf1 at 10240. Ps at 20480, psbuf (2x128) after.
// ===========================================================================
#define ATT_BUF_WORDS 10240
#define ATT_SMEM_WORDS (2 * ATT_BUF_WORDS + 128 + 256)
#define ATT_SMEM_BYTES (ATT_SMEM_WORDS * 4)

__global__ void __launch_bounds__(256, 2)
k_att_mma(const float* __restrict__ P) {
    extern __shared__ __align__(16) uint32_t sm[];
    float* Ps    = (float*)(sm + 2 * ATT_BUF_WORDS);
    float* psbuf = Ps + 128;    // [2][128]

    const int cx = blockIdx.x, h = blockIdx.y, zb = blockIdx.z;
    const int m0 = zb * 128;
    const int tid = threadIdx.x;
    const int wid = tid >> 5;
    const int lane = tid & 31;
    const int g  = lane >> 2;
    const int tg = lane & 3;
    const int wm = wid & 3, wn = wid >> 2;

    if (tid < 128) Ps[tid] = P[h * 256 + cx * 128 + tid];

    const uint32_t smb = smem_u32(sm);
    uint32_t aoff_h[2], aoff_l[2];
#pragma unroll
    for (int mt = 0; mt < 2; mt++) {
        int r = wm * 32 + mt * 16 + (lane & 7) + ((lane >> 3) & 1) * 8;
        aoff_h[mt] = (uint32_t)(r * 20 + (lane >> 4) * 4) * 4;
        aoff_l[mt] = aoff_h[mt] + 2560u * 4;
    }
    uint32_t boff_h[4], boff_l[4];
#pragma unroll
    for (int bn = 0; bn < 4; bn++) {
        int r = wn * 64 + bn * 16 + (lane & 7) + ((lane >> 4) << 3);
        boff_h[bn] = (uint32_t)(5120 + r * 20 + ((lane >> 3) & 1) * 4) * 4;
        boff_l[bn] = boff_h[bn] + 2560u * 4;
    }

    const __nv_bfloat16* Wh = g_Wth + ((size_t)h * 256 + cx * 128) * 256;
    const __nv_bfloat16* Wl = g_Wtl + ((size_t)h * 256 + cx * 128) * 256;

    float acc[2][8][4];
#pragma unroll
    for (int mt = 0; mt < 2; mt++)
#pragma unroll
        for (int j = 0; j < 8; j++)
#pragma unroll
            for (int e = 0; e < 4; e++) acc[mt][j][e] = 0.f;

    auto issue = [&](int ch, uint32_t dstb) {
#pragma unroll
        for (int t = tid; t < 2048; t += 256) {
            int sel = t >> 10;             // 0 = A, 1 = B
            int q = t & 1023;
            int r = q >> 3;
            int j = q & 7;
            int pl = j >> 2;               // 0 hi, 1 lo
            int w4 = (j & 3) * 4;
            if (sel == 0) {
                const void* src = g_d3p + (size_t)(m0 + r) * 256 + pl * 128 + ch * 16 + w4;
                uint32_t dst = dstb + (uint32_t)((pl ? 2560 : 0) + r * 20 + w4) * 4;
                CP16(dst, src);
            } else {
                const __nv_bfloat16* bp = pl ? Wl : Wh;
                const void* src = bp + (size_t)r * 256 + ch * 32 + w4 * 2;
                uint32_t dst = dstb + (uint32_t)((pl ? 7680 : 5120) + r * 20 + w4) * 4;
                CP16(dst, src);
            }
        }
        CP_COMMIT();
    };

    issue(0, smb);

    for (int ch = 0; ch < 8; ch++) {
        const uint32_t bufb = smb + (uint32_t)(ch & 1) * (ATT_BUF_WORDS * 4);
        if (ch + 1 < 8) {
            issue(ch + 1, smb + (uint32_t)((ch + 1) & 1) * (ATT_BUF_WORDS * 4));
            CP_WAIT(1);
        } else {
            CP_WAIT(0);
        }
        __syncthreads();

#pragma unroll
        for (int ks = 0; ks < 2; ks++) {
            const uint32_t kb = (uint32_t)(ks * 8) * 4;
            uint32_t ah[2][4], al[2][4];
            ldsm_x4(ah[0], bufb + aoff_h[0] + kb);
            ldsm_x4(ah[1], bufb + aoff_h[1] + kb);
            ldsm_x4(al[0], bufb + aoff_l[0] + kb);
            ldsm_x4(al[1], bufb + aoff_l[1] + kb);
#pragma unroll
            for (int bn = 0; bn < 4; bn++) {
                uint32_t bh[4], bl[4];
                ldsm_x4(bh, bufb + boff_h[bn] + kb);
                ldsm_x4(bl, bufb + boff_l[bn] + kb);
#pragma unroll
                for (int mt = 0; mt < 2; mt++) {
                    mma16816(acc[mt][2 * bn],     ah[mt], bh[0], bh[1]);
                    mma16816(acc[mt][2 * bn],     ah[mt], bl[0], bl[1]);
                    mma16816(acc[mt][2 * bn],     al[mt], bh[0], bh[1]);
                    mma16816(acc[mt][2 * bn + 1], ah[mt], bh[2], bh[3]);
                    mma16816(acc[mt][2 * bn + 1], ah[mt], bl[2], bl[3]);
                    mma16816(acc[mt][2 * bn + 1], al[mt], bh[2], bh[3]);
                }
            }
        }
        __syncthreads();
    }

    // ---- epilogue: per-row ps over this warp's 64 cols, then cross-warp sum ----
    const float* y2p = g_y2 + (size_t)h * 64 * 256 + cx * 128;
#pragma unroll
    for (int mt = 0; mt < 2; mt++) {
        const int r0 = wm * 32 + mt * 16 + g;
        const int r1 = r0 + 8;
        const int b0 = (m0 + r0) & 63, b1v = (m0 + r1) & 63;
        float ps0 = 0.f, ps1 = 0.f;
#pragma unroll
        for (int j = 0; j < 8; j++) {
            const int cc = wn * 64 + j * 8 + tg * 2;
            const float p0 = Ps[cc], p1 = Ps[cc + 1];
            const float2 y0 = __ldg((const float2*)(y2p + b0 * 256 + cc));
            const float2 y1 = __ldg((const float2*)(y2p + b1v * 256 + cc));
            ps0 += tanhf(acc[mt][j][0] + y0.x) * p0 + tanhf(acc[mt][j][1] + y0.y) * p1;
            ps1 += tanhf(acc[mt][j][2] + y1.x) * p0 + tanhf(acc[mt][j][3] + y1.y) * p1;
        }
        ps0 += __shfl_xor_sync(0xffffffffu, ps0, 1);
        ps0 += __shfl_xor_sync(0xffffffffu, ps0, 2);
        ps1 += __shfl_xor_sync(0xffffffffu, ps1, 1);
        ps1 += __shfl_xor_sync(0xffffffffu, ps1, 2);
        if (tg == 0) {
            psbuf[wn * 128 + r0] = ps0;
            psbuf[wn * 128 + r1] = ps1;
        }
    }
    __syncthreads();
    if (tid < 128) {
        const float v = psbuf[tid] + psbuf[128 + tid];
        const int R = m0 + tid;
        g_attsp[(size_t)cx * (NHEAD * BATCH * SEQ) +
                ((size_t)h * 64 + (R & 63)) * 512 + (R >> 6)] = v;
    }
}

// ===========================================================================
// Row softmax over S=512, summing the two c-half partials. grid 512, blk 256.
// ===========================================================================
__global__ void k_softmax() {
    __shared__ float red[256];
    int row = blockIdx.x, tid = threadIdx.x;
    const float* a0 = g_attsp + (size_t)row * 512;
    const float* a1 = a0 + (size_t)NHEAD * BATCH * SEQ;
    float v0 = a0[tid] + a1[tid];
    float v1 = a0[tid + 256] + a1[tid + 256];
    red[tid] = fmaxf(v0, v1);
    __syncthreads();
    for (int o = 128; o > 0; o >>= 1) {
        if (tid < o) red[tid] = fmaxf(red[tid], red[tid + o]);
        __syncthreads();
    }
    float m = red[0];
    __syncthreads();
    float e0 = expf(v0 - m), e1 = expf(v1 - m);
    red[tid] = e0 + e1;
    __syncthreads();
    for (int o = 128; o > 0; o >>= 1) {
        if (tid < o) red[tid] += red[tid + o];
        __syncthreads();
    }
    float inv = 1.f / red[0];
    g_scores[(size_t)row * 512 + tid]       = e0 * inv;
    g_scores[(size_t)row * 512 + tid + 256] = e1 * inv;
}

// ===========================================================================
// Partial vs over s-chunks. grid (BATCH, 8), block 256.
// ===========================================================================
__global__ void __launch_bounds__(256)
k_out1() {
    __shared__ float sc[512];
    int b = blockIdx.x, sb = blockIdx.y, tid = threadIdx.x;
    for (int i = tid; i < 512; i += 256) {
        int h = i >> 6, ss = i & 63;
        sc[i] = g_scores[((size_t)h * 64 + b) * 512 + sb * 64 + ss];
    }
    __syncthreads();
    float acc[NHEAD] = {0.f, 0.f, 0.f, 0.f, 0.f, 0.f, 0.f, 0.f};
    const float* tvb = g_tv + ((size_t)b * 512 + sb * 64) * 256 + tid;
#pragma unroll 8
    for (int ss = 0; ss < 64; ss++) {
        float t = tvb[(size_t)ss * 256];
#pragma unroll
        for (int h = 0; h < NHEAD; h++) acc[h] = fmaf(sc[h * 64 + ss], t, acc[h]);
    }
#pragma unroll
    for (int h = 0; h < NHEAD; h++)
        g_vsp[((size_t)sb * 64 + b) * 2048 + h * 256 + tid] = acc[h];
}

// ===========================================================================
// Reduce partials + final cc. grid 64, block 128.
// ===========================================================================
__global__ void __launch_bounds__(128)
k_out2(const float* __restrict__ wcc, const float* __restrict__ bcc,
       float* __restrict__ out) {
    __shared__ float vsf[2048];
    int b = blockIdx.x, tid = threadIdx.x;
    for (int i = tid; i < 2048; i += 128) {
        float v = 0.f;
#pragma unroll
        for (int sb = 0; sb < 8; sb++)
            v += g_vsp[((size_t)sb * 64 + b) * 2048 + i];
        vsf[i] = v;
    }
    __syncthreads();
    float o = bcc[tid];
#pragma unroll 8
    for (int i = 0; i < 2048; i++) o = fmaf(vsf[i], wcc[i * 128 + tid], o);
    out[b * 128 + tid] = fmaxf(o, 0.f);
}

// ===========================================================================
extern "C" void kernel_launch(void* const* d_in, const int* in_sizes, int n_in,
                              void* d_out, int out_size) {
    const float* d1  = (const float*)d_in[0];
    const float* d2  = (const float*)d_in[1];
    const float* w1  = (const float*)d_in[2];
    const float* b1  = (const float*)d_in[3];
    const float* W   = (const float*)d_in[4];
    const float* P   = (const float*)d_in[5];
    const float* wv  = (const float*)d_in[6];
    const float* wcc = (const float*)d_in[7];
    const float* bcc = (const float*)d_in[8];
    float* out = (float*)d_out;

    cudaFuncSetAttribute(k_att_mma, cudaFuncAttributeMaxDynamicSharedMemorySize,
                         ATT_SMEM_BYTES);
    cudaFuncSetAttribute(k_proj_mma, cudaFuncAttributeMaxDynamicSharedMemorySize,
                         PROJ_SMEM_BYTES);

    k_d4<<<BATCH, COMP>>>(d1, w1, b1);
    k_y2<<<NHEAD, 256>>>(W);
    k_wsplit<<<10, 256>>>(W, w1, wv);
    k_proj_mma<<<dim3(2, 2, 256), 256, PROJ_SMEM_BYTES>>>(d2, b1);
    k_att_mma<<<dim3(2, NHEAD, SEQ / 2), 256, ATT_SMEM_BYTES>>>(P);
    k_softmax<<<NHEAD * BATCH, 256>>>();
    k_out1<<<dim3(BATCH, 8), 256>>>();
    k_out2<<<BATCH, 128>>>(wcc, bcc, out);
}

// round 12
// speedup vs baseline: 1.0046x; 1.0046x over previous
#include <cuda_runtime.h>
#include <cuda_bf16.h>
#include <cstdint>

#define SEQ   512
#define BATCH 64
#define FEAT  512
#define COMP  256
#define NHEAD 8

// Scratch (allocation-free rule: __device__ globals)
__device__ uint32_t g_d3p[(size_t)SEQ * BATCH * 256];   // d3 bf16 split: [row][128 hi | 128 lo] words
__device__ float g_tv[(size_t)BATCH * SEQ * COMP];      // [64][512][256]
__device__ float g_d4[BATCH * COMP];                    // [64][256]
__device__ float g_y2[NHEAD * BATCH * COMP];            // [8][64][256]
__device__ float g_attsp[2 * NHEAD * BATCH * SEQ];      // two c-half partials
__device__ float g_scores[NHEAD * BATCH * SEQ];
__device__ float g_vsp[8 * BATCH * NHEAD * COMP];       // [8 sb][64][2048]
// W^T bf16 split for k_att: [h][c][k<256]
__device__ __align__(16) __nv_bfloat16 g_Wth[NHEAD * 256 * 256];
__device__ __align__(16) __nv_bfloat16 g_Wtl[NHEAD * 256 * 256];
// w1/wv transposed split for k_proj: [path][c][k<512]
__device__ __align__(16) __nv_bfloat16 g_wpth[2 * 256 * 512];
__device__ __align__(16) __nv_bfloat16 g_wptl[2 * 256 * 512];

__device__ __forceinline__ uint32_t smem_u32(const void* p) {
    uint32_t a;
    asm("{ .reg .u64 t; cvta.to.shared.u64 t, %1; cvt.u32.u64 %0, t; }" : "=r"(a) : "l"(p));
    return a;
}

#define CP16(dst, src) \
    asm volatile("cp.async.ca.shared.global [%0], [%1], 16;" :: "r"(dst), "l"(src) : "memory")
#define CP_COMMIT() asm volatile("cp.async.commit_group;" ::: "memory")
#define CP_WAIT(n)  asm volatile("cp.async.wait_group %0;" :: "n"(n) : "memory")

// bf16 split of a pair of floats -> packed hi and lo words
__device__ __forceinline__ void split2(float a, float b, uint32_t& hi, uint32_t& lo) {
    __nv_bfloat16 ha = __float2bfloat16_rn(a);
    __nv_bfloat16 hb = __float2bfloat16_rn(b);
    __nv_bfloat16 la = __float2bfloat16_rn(a - __bfloat162float(ha));
    __nv_bfloat16 lb = __float2bfloat16_rn(b - __bfloat162float(hb));
    hi = (uint32_t)__bfloat16_as_ushort(ha) | ((uint32_t)__bfloat16_as_ushort(hb) << 16);
    lo = (uint32_t)__bfloat16_as_ushort(la) | ((uint32_t)__bfloat16_as_ushort(lb) << 16);
}

__device__ __forceinline__ void mma16816(float c[4], const uint32_t a[4],
                                         uint32_t b0, uint32_t b1) {
    asm volatile(
        "mma.sync.aligned.m16n8k16.row.col.f32.bf16.bf16.f32 "
        "{%0,%1,%2,%3}, {%4,%5,%6,%7}, {%8,%9}, {%0,%1,%2,%3};"
        : "+f"(c[0]), "+f"(c[1]), "+f"(c[2]), "+f"(c[3])
        : "r"(a[0]), "r"(a[1]), "r"(a[2]), "r"(a[3]), "r"(b0), "r"(b1));
}

__device__ __forceinline__ void ldsm_x4(uint32_t r[4], uint32_t addr) {
    asm volatile("ldmatrix.sync.aligned.m8n8.x4.shared.b16 {%0,%1,%2,%3}, [%4];"
        : "=r"(r[0]), "=r"(r[1]), "=r"(r[2]), "=r"(r[3]) : "r"(addr));
}

// ===========================================================================
// d4 = relu(d1 @ w1 + b1)   [64,256]
// ===========================================================================
__global__ void k_d4(const float* __restrict__ d1, const float* __restrict__ w1,
                     const float* __restrict__ b1) {
    __shared__ float row[FEAT];
    int b = blockIdx.x, c = threadIdx.x;
    for (int i = c; i < FEAT; i += blockDim.x) row[i] = d1[b * FEAT + i];
    __syncthreads();
    float acc = b1[c];
#pragma unroll 8
    for (int d = 0; d < FEAT; d++) acc = fmaf(row[d], w1[d * COMP + c], acc);
    g_d4[b * COMP + c] = fmaxf(acc, 0.f);
}

// ===========================================================================
// 64-row fp32 tile GEMM (round-2 proven). 256 threads, 8x8 microtile.
// ===========================================================================
template <int K, int LDA>
__device__ __forceinline__ void gemm_tile64(const float* __restrict__ A,
                                            const float* __restrict__ Bm,
                                            float acc[8][8]) {
    __shared__ float As[16 * 64];
    __shared__ float Bs[16 * 256];
    int tid  = threadIdx.x;
    int am   = tid >> 2;
    int ak   = (tid & 3) << 2;
    int bn   = (tid & 63) << 2;
    int bk   = (tid >> 6) << 2;
    int rowb = (tid >> 5) << 3;
    int cb   = (tid & 31) << 2;

#pragma unroll
    for (int i = 0; i < 8; i++)
#pragma unroll
        for (int j = 0; j < 8; j++) acc[i][j] = 0.f;

    for (int k0 = 0; k0 < K; k0 += 16) {
        float4 av = *(const float4*)(A + am * LDA + k0 + ak);
        As[(ak + 0) * 64 + am] = av.x;
        As[(ak + 1) * 64 + am] = av.y;
        As[(ak + 2) * 64 + am] = av.z;
        As[(ak + 3) * 64 + am] = av.w;
#pragma unroll
        for (int i = 0; i < 4; i++) {
            *(float4*)(Bs + (bk + i) * 256 + bn) =
                *(const float4*)(Bm + (size_t)(k0 + bk + i) * 256 + bn);
        }
        __syncthreads();
#pragma unroll
        for (int kk = 0; kk < 16; kk++) {
            float4 a0 = *(const float4*)(As + kk * 64 + rowb);
            float4 a1 = *(const float4*)(As + kk * 64 + rowb + 4);
            float4 b0 = *(const float4*)(Bs + kk * 256 + cb);
            float4 b1 = *(const float4*)(Bs + kk * 256 + cb + 128);
            float a[8]  = {a0.x, a0.y, a0.z, a0.w, a1.x, a1.y, a1.z, a1.w};
            float bb[8] = {b0.x, b0.y, b0.z, b0.w, b1.x, b1.y, b1.z, b1.w};
#pragma unroll
            for (int i = 0; i < 8; i++)
#pragma unroll
                for (int j = 0; j < 8; j++)
                    acc[i][j] = fmaf(a[i], bb[j], acc[i][j]);
        }
        __syncthreads();
    }
}

// ===========================================================================
// y2[h][b][c] = d4[b,:] @ W_h[256:512,:]   grid NHEAD, block 256.
// ===========================================================================
__global__ void __launch_bounds__(256)
k_y2(const float* __restrict__ W) {
    int h = blockIdx.x;
    float acc[8][8];
    gemm_tile64<COMP, COMP>(g_d4, W + (size_t)h * 512 * 256 + 256 * 256, acc);
    int tid  = threadIdx.x;
    int rowb = (tid >> 5) << 3;
    int cb   = (tid & 31) << 2;
#pragma unroll
    for (int i = 0; i < 8; i++)
#pragma unroll
        for (int j = 0; j < 8; j++) {
            int c = (j < 4) ? cb + j : cb + 124 + j;
            g_y2[((size_t)h * 64 + rowb + i) * 256 + c] = acc[i][j];
        }
}

// ===========================================================================
// Weight split prep (fused): blocks 0..7 -> W^T split (k_att);
// blocks 8..9 -> w1/wv transposed split (k_proj). grid 10, block 256.
// ===========================================================================
__global__ void __launch_bounds__(256)
k_wsplit(const float* __restrict__ W, const float* __restrict__ w1,
         const float* __restrict__ wv) {
    if (blockIdx.x < 8) {
        int h = blockIdx.x;
        for (int i = threadIdx.x; i < 256 * 256; i += 256) {
            int k = i >> 8, c = i & 255;
            float v = W[((size_t)h * 512 + k) * 256 + c];
            __nv_bfloat16 hi = __float2bfloat16_rn(v);
            __nv_bfloat16 lo = __float2bfloat16_rn(v - __bfloat162float(hi));
            size_t o = ((size_t)h * 256 + c) * 256 + k;
            g_Wth[o] = hi;
            g_Wtl[o] = lo;
        }
    } else {
        int path = blockIdx.x - 8;
        const float* w = path ? wv : w1;
        for (int i = threadIdx.x; i < 256 * 512; i += 256) {
            int c = i >> 9, k = i & 511;
            float v = w[(size_t)k * 256 + c];
            __nv_bfloat16 hi = __float2bfloat16_rn(v);
            __nv_bfloat16 lo = __float2bfloat16_rn(v - __bfloat162float(hi));
            size_t o = ((size_t)path * 256 + c) * 512 + k;
            g_wpth[o] = hi;
            g_wptl[o] = lo;
        }
    }
}

// ===========================================================================
// k_proj via HMMA bf16-split + ldmatrix, 32x64 warp tile.
// grid (2 cx, 2 path, 256 mblk), blk 256. Warps: 4m x 2n over 128x128 tile.
// Smem words: Ah 0, Al 4608, Bh 9216, Bl 13824 (pitch 36), b1s 18432.
// ===========================================================================
#define PROJ_SMEM_WORDS 18560
#define PROJ_SMEM_BYTES (PROJ_SMEM_WORDS * 4)

__global__ void __launch_bounds__(256, 2)
k_proj_mma(const float* __restrict__ d2, const float* __restrict__ b1) {
    extern __shared__ __align__(16) uint32_t sm[];
    uint32_t* Ah = sm;
    uint32_t* Al = sm + 4608;
    uint32_t* Bh = sm + 9216;
    uint32_t* Bl = sm + 13824;
    float*    b1s = (float*)(sm + 18432);

    const int cx = blockIdx.x, path = blockIdx.y, zb = blockIdx.z;
    const int m0 = zb * 128;
    const int tid = threadIdx.x;
    const int wid = tid >> 5;
    const int lane = tid & 31;
    const int g  = lane >> 2;
    const int tg = lane & 3;
    const int wm = wid & 3, wn = wid >> 2;

    if (path == 0 && tid < 128) b1s[tid] = b1[cx * 128 + tid];

    const uint32_t smb = smem_u32(sm);
    uint32_t aaddr_h[2], aaddr_l[2];
#pragma unroll
    for (int mt = 0; mt < 2; mt++) {
        int r = wm * 32 + mt * 16 + (lane & 7) + ((lane >> 3) & 1) * 8;
        aaddr_h[mt] = smb + (uint32_t)(r * 36 + (lane >> 4) * 4) * 4;
        aaddr_l[mt] = aaddr_h[mt] + 4608u * 4;
    }
    uint32_t baddr_h[4], baddr_l[4];
#pragma unroll
    for (int bn = 0; bn < 4; bn++) {
        int r = wn * 64 + bn * 16 + (lane & 7) + ((lane >> 4) << 3);
        baddr_h[bn] = smb + (uint32_t)(9216 + r * 36 + ((lane >> 3) & 1) * 4) * 4;
        baddr_l[bn] = baddr_h[bn] + 4608u * 4;
    }

    float acc[2][8][4];
#pragma unroll
    for (int mt = 0; mt < 2; mt++)
#pragma unroll
        for (int j = 0; j < 8; j++)
#pragma unroll
            for (int e = 0; e < 4; e++) acc[mt][j][e] = 0.f;

    const __nv_bfloat16* Wh = g_wpth + ((size_t)path * 256 + cx * 128) * 512;
    const __nv_bfloat16* Wl = g_wptl + ((size_t)path * 256 + cx * 128) * 512;

    for (int ch = 0; ch < 8; ch++) {
        __syncthreads();
        // A chunk: fp32 -> bf16 hi/lo split inline (128 rows x 64 k)
        for (int t = tid; t < 2048; t += 256) {
            int r = t >> 4, j = t & 15;
            float4 v = *(const float4*)(d2 + (size_t)(m0 + r) * 512 + ch * 64 + j * 4);
            uint32_t hi0, lo0, hi1, lo1;
            split2(v.x, v.y, hi0, lo0);
            split2(v.z, v.w, hi1, lo1);
            Ah[r * 36 + j * 2]     = hi0;
            Ah[r * 36 + j * 2 + 1] = hi1;
            Al[r * 36 + j * 2]     = lo0;
            Al[r * 36 + j * 2 + 1] = lo1;
        }
        for (int t = tid; t < 2048; t += 256) {
            int n = t >> 4, j = t & 15;
            int plane = j >> 3, j8 = j & 7;
            const uint4* srow = (const uint4*)((plane ? Wl : Wh) + (size_t)n * 512 + ch * 64);
            uint32_t* dstp = (plane ? Bl : Bh) + n * 36 + j8 * 4;
            *(uint4*)dstp = srow[j8];
        }
        __syncthreads();

#pragma unroll
        for (int ks = 0; ks < 4; ks++) {
            const uint32_t kb = (uint32_t)(ks * 8) * 4;
            uint32_t ah[2][4], al[2][4];
            ldsm_x4(ah[0], aaddr_h[0] + kb);
            ldsm_x4(ah[1], aaddr_h[1] + kb);
            ldsm_x4(al[0], aaddr_l[0] + kb);
            ldsm_x4(al[1], aaddr_l[1] + kb);
#pragma unroll
            for (int bn = 0; bn < 4; bn++) {
                uint32_t bh[4], bl[4];
                ldsm_x4(bh, baddr_h[bn] + kb);
                ldsm_x4(bl, baddr_l[bn] + kb);
#pragma unroll
                for (int mt = 0; mt < 2; mt++) {
                    mma16816(acc[mt][2 * bn],     ah[mt], bh[0], bh[1]);
                    mma16816(acc[mt][2 * bn],     ah[mt], bl[0], bl[1]);
                    mma16816(acc[mt][2 * bn],     al[mt], bh[0], bh[1]);
                    mma16816(acc[mt][2 * bn + 1], ah[mt], bh[2], bh[3]);
                    mma16816(acc[mt][2 * bn + 1], ah[mt], bl[2], bl[3]);
                    mma16816(acc[mt][2 * bn + 1], al[mt], bh[2], bh[3]);
                }
            }
        }
    }

#pragma unroll
    for (int mt = 0; mt < 2; mt++) {
        const int R0 = m0 + wm * 32 + mt * 16 + g;
        const int R1 = R0 + 8;
        if (path == 0) {
            uint32_t* dst0 = g_d3p + (size_t)R0 * 256;
            uint32_t* dst1 = g_d3p + (size_t)R1 * 256;
#pragma unroll
            for (int j = 0; j < 8; j++) {
                const int ch_ = wn * 64 + j * 8 + tg * 2;      // col within cx half
                const int word = cx * 64 + wn * 32 + j * 4 + tg;
                const float bb0 = b1s[ch_], bb1 = b1s[ch_ + 1];
                uint32_t hi, lo;
                float v0 = fmaxf(acc[mt][j][0] + bb0, 0.f);
                float v1 = fmaxf(acc[mt][j][1] + bb1, 0.f);
                split2(v0, v1, hi, lo);
                dst0[word] = hi; dst0[128 + word] = lo;
                float v2 = fmaxf(acc[mt][j][2] + bb0, 0.f);
                float v3 = fmaxf(acc[mt][j][3] + bb1, 0.f);
                split2(v2, v3, hi, lo);
                dst1[word] = hi; dst1[128 + word] = lo;
            }
        } else {
            const int s0 = R0 >> 6, b0i = R0 & 63;
            const int s1 = R1 >> 6, b1i = R1 & 63;
            float* t0 = g_tv + ((size_t)b0i * 512 + s0) * 256 + cx * 128;
            float* t1 = g_tv + ((size_t)b1i * 512 + s1) * 256 + cx * 128;
#pragma unroll
            for (int j = 0; j < 8; j++) {
                const int cc = wn * 64 + j * 8 + tg * 2;
                *(float2*)(t0 + cc) = make_float2(tanhf(acc[mt][j][0]), tanhf(acc[mt][j][1]));
                *(float2*)(t1 + cc) = make_float2(tanhf(acc[mt][j][2]), tanhf(acc[mt][j][3]));
            }
        }
    }
}

// ===========================================================================
// k_att via HMMA + cp.async 2-stage pipeline, 32x64 warp tile.
// grid (2 cx, 8 h, 256), blk 256. k=32 chunks (8), double-buffered.
// Buf layout (words, pitch 20): Ah [0,2560) Al [2560,5120) Bh [5120,7680)
// Bl [7680,10240); buf1 at 10240. Ps at 20480, psbuf (2x128) after.
// ===========================================================================
#define ATT_BUF_WORDS 10240
#define ATT_SMEM_WORDS (2 * ATT_BUF_WORDS + 128 + 256)
#define ATT_SMEM_BYTES (ATT_SMEM_WORDS * 4)

__global__ void __launch_bounds__(256, 2)
k_att_mma(const float* __restrict__ P) {
    extern __shared__ __align__(16) uint32_t sm[];
    float* Ps    = (float*)(sm + 2 * ATT_BUF_WORDS);
    float* psbuf = Ps + 128;    // [2][128]

    const int cx = blockIdx.x, h = blockIdx.y, zb = blockIdx.z;
    const int m0 = zb * 128;
    const int tid = threadIdx.x;
    const int wid = tid >> 5;
    const int lane = tid & 31;
    const int g  = lane >> 2;
    const int tg = lane & 3;
    const int wm = wid & 3, wn = wid >> 2;

    if (tid < 128) Ps[tid] = P[h * 256 + cx * 128 + tid];

    const uint32_t smb = smem_u32(sm);
    uint32_t aoff_h[2], aoff_l[2];
#pragma unroll
    for (int mt = 0; mt < 2; mt++) {
        int r = wm * 32 + mt * 16 + (lane & 7) + ((lane >> 3) & 1) * 8;
        aoff_h[mt] = (uint32_t)(r * 20 + (lane >> 4) * 4) * 4;
        aoff_l[mt] = aoff_h[mt] + 2560u * 4;
    }
    uint32_t boff_h[4], boff_l[4];
#pragma unroll
    for (int bn = 0; bn < 4; bn++) {
        int r = wn * 64 + bn * 16 + (lane & 7) + ((lane >> 4) << 3);
        boff_h[bn] = (uint32_t)(5120 + r * 20 + ((lane >> 3) & 1) * 4) * 4;
        boff_l[bn] = boff_h[bn] + 2560u * 4;
    }

    const __nv_bfloat16* Wh = g_Wth + ((size_t)h * 256 + cx * 128) * 256;
    const __nv_bfloat16* Wl = g_Wtl + ((size_t)h * 256 + cx * 128) * 256;

    float acc[2][8][4];
#pragma unroll
    for (int mt = 0; mt < 2; mt++)
#pragma unroll
        for (int j = 0; j < 8; j++)
#pragma unroll
            for (int e = 0; e < 4; e++) acc[mt][j][e] = 0.f;

    auto issue = [&](int ch, uint32_t dstb) {
#pragma unroll
        for (int t = tid; t < 2048; t += 256) {
            int sel = t >> 10;             // 0 = A, 1 = B
            int q = t & 1023;
            int r = q >> 3;
            int j = q & 7;
            int pl = j >> 2;               // 0 hi, 1 lo
            int w4 = (j & 3) * 4;
            if (sel == 0) {
                const void* src = g_d3p + (size_t)(m0 + r) * 256 + pl * 128 + ch * 16 + w4;
                uint32_t dst = dstb + (uint32_t)((pl ? 2560 : 0) + r * 20 + w4) * 4;
                CP16(dst, src);
            } else {
                const __nv_bfloat16* bp = pl ? Wl : Wh;
                const void* src = bp + (size_t)r * 256 + ch * 32 + w4 * 2;
                uint32_t dst = dstb + (uint32_t)((pl ? 7680 : 5120) + r * 20 + w4) * 4;
                CP16(dst, src);
            }
        }
        CP_COMMIT();
    };

    issue(0, smb);

    for (int ch = 0; ch < 8; ch++) {
        const uint32_t bufb = smb + (uint32_t)(ch & 1) * (ATT_BUF_WORDS * 4);
        if (ch + 1 < 8) {
            issue(ch + 1, smb + (uint32_t)((ch + 1) & 1) * (ATT_BUF_WORDS * 4));
            CP_WAIT(1);
        } else {
            CP_WAIT(0);
        }
        __syncthreads();

#pragma unroll
        for (int ks = 0; ks < 2; ks++) {
            const uint32_t kb = (uint32_t)(ks * 8) * 4;
            uint32_t ah[2][4], al[2][4];
            ldsm_x4(ah[0], bufb + aoff_h[0] + kb);
            ldsm_x4(ah[1], bufb + aoff_h[1] + kb);
            ldsm_x4(al[0], bufb + aoff_l[0] + kb);
            ldsm_x4(al[1], bufb + aoff_l[1] + kb);
#pragma unroll
            for (int bn = 0; bn < 4; bn++) {
                uint32_t bh[4], bl[4];
                ldsm_x4(bh, bufb + boff_h[bn] + kb);
                ldsm_x4(bl, bufb + boff_l[bn] + kb);
#pragma unroll
                for (int mt = 0; mt < 2; mt++) {
                    mma16816(acc[mt][2 * bn],     ah[mt], bh[0], bh[1]);
                    mma16816(acc[mt][2 * bn],     ah[mt], bl[0], bl[1]);
                    mma16816(acc[mt][2 * bn],     al[mt], bh[0], bh[1]);
                    mma16816(acc[mt][2 * bn + 1], ah[mt], bh[2], bh[3]);
                    mma16816(acc[mt][2 * bn + 1], ah[mt], bl[2], bl[3]);
                    mma16816(acc[mt][2 * bn + 1], al[mt], bh[2], bh[3]);
                }
            }
        }
        __syncthreads();
    }

    // ---- epilogue: per-row ps over this warp's 64 cols, then cross-warp sum ----
    const float* y2p = g_y2 + (size_t)h * 64 * 256 + cx * 128;
#pragma unroll
    for (int mt = 0; mt < 2; mt++) {
        const int r0 = wm * 32 + mt * 16 + g;
        const int r1 = r0 + 8;
        const int b0 = (m0 + r0) & 63, b1v = (m0 + r1) & 63;
        float ps0 = 0.f, ps1 = 0.f;
#pragma unroll
        for (int j = 0; j < 8; j++) {
            const int cc = wn * 64 + j * 8 + tg * 2;
            const float p0 = Ps[cc], p1 = Ps[cc + 1];
            const float2 y0 = __ldg((const float2*)(y2p + b0 * 256 + cc));
            const float2 y1 = __ldg((const float2*)(y2p + b1v * 256 + cc));
            ps0 += tanhf(acc[mt][j][0] + y0.x) * p0 + tanhf(acc[mt][j][1] + y0.y) * p1;
            ps1 += tanhf(acc[mt][j][2] + y1.x) * p0 + tanhf(acc[mt][j][3] + y1.y) * p1;
        }
        ps0 += __shfl_xor_sync(0xffffffffu, ps0, 1);
        ps0 += __shfl_xor_sync(0xffffffffu, ps0, 2);
        ps1 += __shfl_xor_sync(0xffffffffu, ps1, 1);
        ps1 += __shfl_xor_sync(0xffffffffu, ps1, 2);
        if (tg == 0) {
            psbuf[wn * 128 + r0] = ps0;
            psbuf[wn * 128 + r1] = ps1;
        }
    }
    __syncthreads();
    if (tid < 128) {
        const float v = psbuf[tid] + psbuf[128 + tid];
        const int R = m0 + tid;
        g_attsp[(size_t)cx * (NHEAD * BATCH * SEQ) +
                ((size_t)h * 64 + (R & 63)) * 512 + (R >> 6)] = v;
    }
}

// ===========================================================================
// Row softmax over S=512, summing the two c-half partials. grid 512, blk 256.
// ===========================================================================
__global__ void k_softmax() {
    __shared__ float red[256];
    int row = blockIdx.x, tid = threadIdx.x;
    const float* a0 = g_attsp + (size_t)row * 512;
    const float* a1 = a0 + (size_t)NHEAD * BATCH * SEQ;
    float v0 = a0[tid] + a1[tid];
    float v1 = a0[tid + 256] + a1[tid + 256];
    red[tid] = fmaxf(v0, v1);
    __syncthreads();
    for (int o = 128; o > 0; o >>= 1) {
        if (tid < o) red[tid] = fmaxf(red[tid], red[tid + o]);
        __syncthreads();
    }
    float m = red[0];
    __syncthreads();
    float e0 = expf(v0 - m), e1 = expf(v1 - m);
    red[tid] = e0 + e1;
    __syncthreads();
    for (int o = 128; o > 0; o >>= 1) {
        if (tid < o) red[tid] += red[tid + o];
        __syncthreads();
    }
    float inv = 1.f / red[0];
    g_scores[(size_t)row * 512 + tid]       = e0 * inv;
    g_scores[(size_t)row * 512 + tid + 256] = e1 * inv;
}

// ===========================================================================
// Partial vs over s-chunks. grid (BATCH, 8), block 256.
// ===========================================================================
__global__ void __launch_bounds__(256)
k_out1() {
    __shared__ float sc[512];
    int b = blockIdx.x, sb = blockIdx.y, tid = threadIdx.x;
    for (int i = tid; i < 512; i += 256) {
        int h = i >> 6, ss = i & 63;
        sc[i] = g_scores[((size_t)h * 64 + b) * 512 + sb * 64 + ss];
    }
    __syncthreads();
    float acc[NHEAD] = {0.f, 0.f, 0.f, 0.f, 0.f, 0.f, 0.f, 0.f};
    const float* tvb = g_tv + ((size_t)b * 512 + sb * 64) * 256 + tid;
#pragma unroll 8
    for (int ss = 0; ss < 64; ss++) {
        float t = tvb[(size_t)ss * 256];
#pragma unroll
        for (int h = 0; h < NHEAD; h++) acc[h] = fmaf(sc[h * 64 + ss], t, acc[h]);
    }
#pragma unroll
    for (int h = 0; h < NHEAD; h++)
        g_vsp[((size_t)sb * 64 + b) * 2048 + h * 256 + tid] = acc[h];
}

// ===========================================================================
// Reduce partials + final cc. grid 64, block 128.
// ===========================================================================
__global__ void __launch_bounds__(128)
k_out2(const float* __restrict__ wcc, const float* __restrict__ bcc,
       float* __restrict__ out) {
    __shared__ float vsf[2048];
    int b = blockIdx.x, tid = threadIdx.x;
    for (int i = tid; i < 2048; i += 128) {
        float v = 0.f;
#pragma unroll
        for (int sb = 0; sb < 8; sb++)
            v += g_vsp[((size_t)sb * 64 + b) * 2048 + i];
        vsf[i] = v;
    }
    __syncthreads();
    float o = bcc[tid];
#pragma unroll 8
    for (int i = 0; i < 2048; i++) o = fmaf(vsf[i], wcc[i * 128 + tid], o);
    out[b * 128 + tid] = fmaxf(o, 0.f);
}

// ===========================================================================
extern "C" void kernel_launch(void* const* d_in, const int* in_sizes, int n_in,
                              void* d_out, int out_size) {
    const float* d1  = (const float*)d_in[0];
    const float* d2  = (const float*)d_in[1];
    const float* w1  = (const float*)d_in[2];
    const float* b1  = (const float*)d_in[3];
    const float* W   = (const float*)d_in[4];
    const float* P   = (const float*)d_in[5];
    const float* wv  = (const float*)d_in[6];
    const float* wcc = (const float*)d_in[7];
    const float* bcc = (const float*)d_in[8];
    float* out = (float*)d_out;

    cudaFuncSetAttribute(k_att_mma, cudaFuncAttributeMaxDynamicSharedMemorySize,
                         ATT_SMEM_BYTES);
    cudaFuncSetAttribute(k_proj_mma, cudaFuncAttributeMaxDynamicSharedMemorySize,
                         PROJ_SMEM_BYTES);

    k_d4<<<BATCH, COMP>>>(d1, w1, b1);
    k_y2<<<NHEAD, 256>>>(W);
    k_wsplit<<<10, 256>>>(W, w1, wv);
    k_proj_mma<<<dim3(2, 2, 256), 256, PROJ_SMEM_BYTES>>>(d2, b1);
    k_att_mma<<<dim3(2, NHEAD, SEQ / 2), 256, ATT_SMEM_BYTES>>>(P);
    k_softmax<<<NHEAD * BATCH, 256>>>();
    k_out1<<<dim3(BATCH, 8), 256>>>();
    k_out2<<<BATCH, 128>>>(wcc, bcc, out);
}

// round 13
// speedup vs baseline: 1.0122x; 1.0075x over previous
#include <cuda_runtime.h>
#include <cuda_bf16.h>
#include <cstdint>

#define SEQ   512
#define BATCH 64
#define FEAT  512
#define COMP  256
#define NHEAD 8

// Scratch (allocation-free rule: __device__ globals)
__device__ uint32_t g_d3p[(size_t)SEQ * BATCH * 256];   // d3 bf16 split: [row][128 hi | 128 lo] words
__device__ float g_tv[(size_t)BATCH * SEQ * COMP];      // [64][512][256]
__device__ float g_d4[BATCH * COMP];                    // [64][256]
__device__ float g_y2[NHEAD * BATCH * COMP];            // [8][64][256]
__device__ float g_attsp[2 * NHEAD * BATCH * SEQ];      // two c-half partials
__device__ float g_scores[NHEAD * BATCH * SEQ];
__device__ float g_vsp[8 * BATCH * NHEAD * COMP];       // [8 sb][64][2048]
// W^T bf16 split for k_att: [h][c][k<256]
__device__ __align__(16) __nv_bfloat16 g_Wth[NHEAD * 256 * 256];
__device__ __align__(16) __nv_bfloat16 g_Wtl[NHEAD * 256 * 256];
// w1/wv transposed split for k_proj: [path][c][k<512]
__device__ __align__(16) __nv_bfloat16 g_wpth[2 * 256 * 512];
__device__ __align__(16) __nv_bfloat16 g_wptl[2 * 256 * 512];

__device__ __forceinline__ uint32_t smem_u32(const void* p) {
    uint32_t a;
    asm("{ .reg .u64 t; cvta.to.shared.u64 t, %1; cvt.u32.u64 %0, t; }" : "=r"(a) : "l"(p));
    return a;
}

#define CP16(dst, src) \
    asm volatile("cp.async.ca.shared.global [%0], [%1], 16;" :: "r"(dst), "l"(src) : "memory")
#define CP_COMMIT() asm volatile("cp.async.commit_group;" ::: "memory")
#define CP_WAIT(n)  asm volatile("cp.async.wait_group %0;" :: "n"(n) : "memory")

// bf16 split of a pair of floats -> packed hi and lo words
__device__ __forceinline__ void split2(float a, float b, uint32_t& hi, uint32_t& lo) {
    __nv_bfloat16 ha = __float2bfloat16_rn(a);
    __nv_bfloat16 hb = __float2bfloat16_rn(b);
    __nv_bfloat16 la = __float2bfloat16_rn(a - __bfloat162float(ha));
    __nv_bfloat16 lb = __float2bfloat16_rn(b - __bfloat162float(hb));
    hi = (uint32_t)__bfloat16_as_ushort(ha) | ((uint32_t)__bfloat16_as_ushort(hb) << 16);
    lo = (uint32_t)__bfloat16_as_ushort(la) | ((uint32_t)__bfloat16_as_ushort(lb) << 16);
}

__device__ __forceinline__ void mma16816(float c[4], const uint32_t a[4],
                                         uint32_t b0, uint32_t b1) {
    asm volatile(
        "mma.sync.aligned.m16n8k16.row.col.f32.bf16.bf16.f32 "
        "{%0,%1,%2,%3}, {%4,%5,%6,%7}, {%8,%9}, {%0,%1,%2,%3};"
        : "+f"(c[0]), "+f"(c[1]), "+f"(c[2]), "+f"(c[3])
        : "r"(a[0]), "r"(a[1]), "r"(a[2]), "r"(a[3]), "r"(b0), "r"(b1));
}

__device__ __forceinline__ void ldsm_x4(uint32_t r[4], uint32_t addr) {
    asm volatile("ldmatrix.sync.aligned.m8n8.x4.shared.b16 {%0,%1,%2,%3}, [%4];"
        : "=r"(r[0]), "=r"(r[1]), "=r"(r[2]), "=r"(r[3]) : "r"(addr));
}

// ===========================================================================
// d4 = relu(d1 @ w1 + b1)   [64,256]
// ===========================================================================
__global__ void k_d4(const float* __restrict__ d1, const float* __restrict__ w1,
                     const float* __restrict__ b1) {
    __shared__ float row[FEAT];
    int b = blockIdx.x, c = threadIdx.x;
    for (int i = c; i < FEAT; i += blockDim.x) row[i] = d1[b * FEAT + i];
    __syncthreads();
    float acc = b1[c];
#pragma unroll 8
    for (int d = 0; d < FEAT; d++) acc = fmaf(row[d], w1[d * COMP + c], acc);
    g_d4[b * COMP + c] = fmaxf(acc, 0.f);
}

// ===========================================================================
// 64-row fp32 tile GEMM (round-2 proven). 256 threads, 8x8 microtile.
// ===========================================================================
template <int K, int LDA>
__device__ __forceinline__ void gemm_tile64(const float* __restrict__ A,
                                            const float* __restrict__ Bm,
                                            float acc[8][8]) {
    __shared__ float As[16 * 64];
    __shared__ float Bs[16 * 256];
    int tid  = threadIdx.x;
    int am   = tid >> 2;
    int ak   = (tid & 3) << 2;
    int bn   = (tid & 63) << 2;
    int bk   = (tid >> 6) << 2;
    int rowb = (tid >> 5) << 3;
    int cb   = (tid & 31) << 2;

#pragma unroll
    for (int i = 0; i < 8; i++)
#pragma unroll
        for (int j = 0; j < 8; j++) acc[i][j] = 0.f;

    for (int k0 = 0; k0 < K; k0 += 16) {
        float4 av = *(const float4*)(A + am * LDA + k0 + ak);
        As[(ak + 0) * 64 + am] = av.x;
        As[(ak + 1) * 64 + am] = av.y;
        As[(ak + 2) * 64 + am] = av.z;
        As[(ak + 3) * 64 + am] = av.w;
#pragma unroll
        for (int i = 0; i < 4; i++) {
            *(float4*)(Bs + (bk + i) * 256 + bn) =
                *(const float4*)(Bm + (size_t)(k0 + bk + i) * 256 + bn);
        }
        __syncthreads();
#pragma unroll
        for (int kk = 0; kk < 16; kk++) {
            float4 a0 = *(const float4*)(As + kk * 64 + rowb);
            float4 a1 = *(const float4*)(As + kk * 64 + rowb + 4);
            float4 b0 = *(const float4*)(Bs + kk * 256 + cb);
            float4 b1 = *(const float4*)(Bs + kk * 256 + cb + 128);
            float a[8]  = {a0.x, a0.y, a0.z, a0.w, a1.x, a1.y, a1.z, a1.w};
            float bb[8] = {b0.x, b0.y, b0.z, b0.w, b1.x, b1.y, b1.z, b1.w};
#pragma unroll
            for (int i = 0; i < 8; i++)
#pragma unroll
                for (int j = 0; j < 8; j++)
                    acc[i][j] = fmaf(a[i], bb[j], acc[i][j]);
        }
        __syncthreads();
    }
}

// ===========================================================================
// y2[h][b][c] = d4[b,:] @ W_h[256:512,:]   grid NHEAD, block 256.
// ===========================================================================
__global__ void __launch_bounds__(256)
k_y2(const float* __restrict__ W) {
    int h = blockIdx.x;
    float acc[8][8];
    gemm_tile64<COMP, COMP>(g_d4, W + (size_t)h * 512 * 256 + 256 * 256, acc);
    int tid  = threadIdx.x;
    int rowb = (tid >> 5) << 3;
    int cb   = (tid & 31) << 2;
#pragma unroll
    for (int i = 0; i < 8; i++)
#pragma unroll
        for (int j = 0; j < 8; j++) {
            int c = (j < 4) ? cb + j : cb + 124 + j;
            g_y2[((size_t)h * 64 + rowb + i) * 256 + c] = acc[i][j];
        }
}

// ===========================================================================
// Weight split prep (fused): blocks 0..7 -> W^T split (k_att);
// blocks 8..9 -> w1/wv transposed split (k_proj). grid 10, block 256.
// ===========================================================================
__global__ void __launch_bounds__(256)
k_wsplit(const float* __restrict__ W, const float* __restrict__ w1,
         const float* __restrict__ wv) {
    if (blockIdx.x < 8) {
        int h = blockIdx.x;
        for (int i = threadIdx.x; i < 256 * 256; i += 256) {
            int k = i >> 8, c = i & 255;
            float v = W[((size_t)h * 512 + k) * 256 + c];
            __nv_bfloat16 hi = __float2bfloat16_rn(v);
            __nv_bfloat16 lo = __float2bfloat16_rn(v - __bfloat162float(hi));
            size_t o = ((size_t)h * 256 + c) * 256 + k;
            g_Wth[o] = hi;
            g_Wtl[o] = lo;
        }
    } else {
        int path = blockIdx.x - 8;
        const float* w = path ? wv : w1;
        for (int i = threadIdx.x; i < 256 * 512; i += 256) {
            int c = i >> 9, k = i & 511;
            float v = w[(size_t)k * 256 + c];
            __nv_bfloat16 hi = __float2bfloat16_rn(v);
            __nv_bfloat16 lo = __float2bfloat16_rn(v - __bfloat162float(hi));
            size_t o = ((size_t)path * 256 + c) * 512 + k;
            g_wpth[o] = hi;
            g_wptl[o] = lo;
        }
    }
}

// ===========================================================================
// k_proj via HMMA bf16-split + ldmatrix, dependency-distance-2 MMA order.
// grid (2 cx, 2 path, 256 mblk), blk 256. 16x128 warp tile (round-8 layout).
// Smem words: Ah 0, Al 4608, Bh 9216, Bl 13824 (pitch 36), b1s 18432.
// ===========================================================================
#define PROJ_SMEM_WORDS 18560
#define PROJ_SMEM_BYTES (PROJ_SMEM_WORDS * 4)

__global__ void __launch_bounds__(256, 2)
k_proj_mma(const float* __restrict__ d2, const float* __restrict__ b1) {
    extern __shared__ __align__(16) uint32_t sm[];
    uint32_t* Ah = sm;
    uint32_t* Al = sm + 4608;
    uint32_t* Bh = sm + 9216;
    uint32_t* Bl = sm + 13824;
    float*    b1s = (float*)(sm + 18432);

    const int cx = blockIdx.x, path = blockIdx.y, zb = blockIdx.z;
    const int m0 = zb * 128;
    const int tid = threadIdx.x;
    const int wid = tid >> 5;
    const int lane = tid & 31;
    const int g  = lane >> 2;
    const int tg = lane & 3;
    const int m0w = wid * 16;

    if (path == 0 && tid < 128) b1s[tid] = b1[cx * 128 + tid];

    const uint32_t smb = smem_u32(sm);
    const int arow = m0w + (lane & 7) + ((lane >> 3) & 1) * 8;
    const int akoff = (lane >> 4) * 4;
    const uint32_t aaddr_h = smb + (uint32_t)(arow * 36 + akoff) * 4;
    const uint32_t aaddr_l = aaddr_h + 4608u * 4;
    const int brow = (lane & 7) + ((lane >> 4) << 3);
    const int bkoff = ((lane >> 3) & 1) * 4;
    const uint32_t baddr_h = smb + (uint32_t)(9216 + brow * 36 + bkoff) * 4;
    const uint32_t baddr_l = baddr_h + 4608u * 4;

    float acc[16][4];
#pragma unroll
    for (int n8 = 0; n8 < 16; n8++)
#pragma unroll
        for (int e = 0; e < 4; e++) acc[n8][e] = 0.f;

    const __nv_bfloat16* Wh = g_wpth + ((size_t)path * 256 + cx * 128) * 512;
    const __nv_bfloat16* Wl = g_wptl + ((size_t)path * 256 + cx * 128) * 512;

    for (int ch = 0; ch < 8; ch++) {
        __syncthreads();
        for (int t = tid; t < 2048; t += 256) {
            int r = t >> 4, j = t & 15;
            float4 v = *(const float4*)(d2 + (size_t)(m0 + r) * 512 + ch * 64 + j * 4);
            uint32_t hi0, lo0, hi1, lo1;
            split2(v.x, v.y, hi0, lo0);
            split2(v.z, v.w, hi1, lo1);
            Ah[r * 36 + j * 2]     = hi0;
            Ah[r * 36 + j * 2 + 1] = hi1;
            Al[r * 36 + j * 2]     = lo0;
            Al[r * 36 + j * 2 + 1] = lo1;
        }
        for (int t = tid; t < 2048; t += 256) {
            int n = t >> 4, j = t & 15;
            int plane = j >> 3, j8 = j & 7;
            const uint4* srow = (const uint4*)((plane ? Wl : Wh) + (size_t)n * 512 + ch * 64);
            uint32_t* dstp = (plane ? Bl : Bh) + n * 36 + j8 * 4;
            *(uint4*)dstp = srow[j8];
        }
        __syncthreads();

#pragma unroll
        for (int ks = 0; ks < 4; ks++) {
            const uint32_t kb = (uint32_t)(ks * 8) * 4;
            uint32_t ah[4], al[4];
            ldsm_x4(ah, aaddr_h + kb);
            ldsm_x4(al, aaddr_l + kb);
            // pass 1: bh (hh + lh), same-acc distance 2
#pragma unroll
            for (int p = 0; p < 8; p++) {
                uint32_t bh[4];
                ldsm_x4(bh, baddr_h + (uint32_t)(p * 16 * 36) * 4 + kb);
                mma16816(acc[2 * p],     ah, bh[0], bh[1]);
                mma16816(acc[2 * p + 1], ah, bh[2], bh[3]);
                mma16816(acc[2 * p],     al, bh[0], bh[1]);
                mma16816(acc[2 * p + 1], al, bh[2], bh[3]);
            }
            // pass 2: bl (hl), all independent within pass
#pragma unroll
            for (int p = 0; p < 8; p++) {
                uint32_t bl[4];
                ldsm_x4(bl, baddr_l + (uint32_t)(p * 16 * 36) * 4 + kb);
                mma16816(acc[2 * p],     ah, bl[0], bl[1]);
                mma16816(acc[2 * p + 1], ah, bl[2], bl[3]);
            }
        }
    }

    const int r0 = m0w + g, r1 = r0 + 8;
    const int R0 = m0 + r0, R1 = m0 + r1;
    if (path == 0) {
        uint32_t* dst0 = g_d3p + (size_t)R0 * 256;
        uint32_t* dst1 = g_d3p + (size_t)R1 * 256;
#pragma unroll
        for (int n8 = 0; n8 < 16; n8++) {
            const int cc = n8 * 8 + tg * 2;
            const int word = cx * 64 + n8 * 4 + tg;
            const float bb0 = b1s[cc], bb1 = b1s[cc + 1];
            uint32_t hi, lo;
            float v0 = fmaxf(acc[n8][0] + bb0, 0.f);
            float v1 = fmaxf(acc[n8][1] + bb1, 0.f);
            split2(v0, v1, hi, lo);
            dst0[word] = hi; dst0[128 + word] = lo;
            float v2 = fmaxf(acc[n8][2] + bb0, 0.f);
            float v3 = fmaxf(acc[n8][3] + bb1, 0.f);
            split2(v2, v3, hi, lo);
            dst1[word] = hi; dst1[128 + word] = lo;
        }
    } else {
        const int s0 = R0 >> 6, b0i = R0 & 63;
        const int s1 = R1 >> 6, b1i = R1 & 63;
        float* t0 = g_tv + ((size_t)b0i * 512 + s0) * 256 + cx * 128;
        float* t1 = g_tv + ((size_t)b1i * 512 + s1) * 256 + cx * 128;
#pragma unroll
        for (int n8 = 0; n8 < 16; n8++) {
            const int cc = n8 * 8 + tg * 2;
            *(float2*)(t0 + cc) = make_float2(tanhf(acc[n8][0]), tanhf(acc[n8][1]));
            *(float2*)(t1 + cc) = make_float2(tanhf(acc[n8][2]), tanhf(acc[n8][3]));
        }
    }
}

// ===========================================================================
// k_att via HMMA + cp.async 2-stage pipeline, dep-distance-2 MMA order.
// grid (2 cx, 8 h, 256), blk 256. k=32 chunks (8), double-buffered.
// Buf layout (words, pitch 20): Ah [0,2560) Al [2560,5120) Bh [5120,7680)
// Bl [7680,10240); buf1 at 10240. Ps at word 20480.
// ===========================================================================
#define ATT_BUF_WORDS 10240
#define ATT_SMEM_WORDS (2 * ATT_BUF_WORDS + 128)
#define ATT_SMEM_BYTES (ATT_SMEM_WORDS * 4)

__global__ void __launch_bounds__(256, 2)
k_att_mma(const float* __restrict__ P) {
    extern __shared__ __align__(16) uint32_t sm[];
    float* Ps = (float*)(sm + 2 * ATT_BUF_WORDS);

    const int cx = blockIdx.x, h = blockIdx.y, zb = blockIdx.z;
    const int m0 = zb * 128;
    const int tid = threadIdx.x;
    const int wid = tid >> 5;
    const int lane = tid & 31;
    const int g  = lane >> 2;
    const int tg = lane & 3;
    const int m0w = wid * 16;

    if (tid < 128) Ps[tid] = P[h * 256 + cx * 128 + tid];

    const uint32_t smb = smem_u32(sm);
    const int arow = m0w + (lane & 7) + ((lane >> 3) & 1) * 8;
    const int akoff = (lane >> 4) * 4;
    const uint32_t aoff_h = (uint32_t)(arow * 20 + akoff) * 4;
    const uint32_t aoff_l = aoff_h + 2560u * 4;
    const int brow = (lane & 7) + ((lane >> 4) << 3);
    const int bkoff = ((lane >> 3) & 1) * 4;
    const uint32_t boff_h = (uint32_t)(5120 + brow * 20 + bkoff) * 4;
    const uint32_t boff_l = boff_h + 2560u * 4;

    const __nv_bfloat16* Wh = g_Wth + ((size_t)h * 256 + cx * 128) * 256;
    const __nv_bfloat16* Wl = g_Wtl + ((size_t)h * 256 + cx * 128) * 256;

    float acc[16][4];
#pragma unroll
    for (int n8 = 0; n8 < 16; n8++)
#pragma unroll
        for (int e = 0; e < 4; e++) acc[n8][e] = 0.f;

    auto issue = [&](int ch, uint32_t dstb) {
#pragma unroll
        for (int t = tid; t < 2048; t += 256) {
            int sel = t >> 10;             // 0 = A, 1 = B
            int q = t & 1023;
            int r = q >> 3;
            int j = q & 7;
            int pl = j >> 2;               // 0 hi, 1 lo
            int w4 = (j & 3) * 4;
            if (sel == 0) {
                const void* src = g_d3p + (size_t)(m0 + r) * 256 + pl * 128 + ch * 16 + w4;
                uint32_t dst = dstb + (uint32_t)((pl ? 2560 : 0) + r * 20 + w4) * 4;
                CP16(dst, src);
            } else {
                const __nv_bfloat16* bp = pl ? Wl : Wh;
                const void* src = bp + (size_t)r * 256 + ch * 32 + w4 * 2;
                uint32_t dst = dstb + (uint32_t)((pl ? 7680 : 5120) + r * 20 + w4) * 4;
                CP16(dst, src);
            }
        }
        CP_COMMIT();
    };

    issue(0, smb);

    for (int ch = 0; ch < 8; ch++) {
        const uint32_t bufb = smb + (uint32_t)(ch & 1) * (ATT_BUF_WORDS * 4);
        if (ch + 1 < 8) {
            issue(ch + 1, smb + (uint32_t)((ch + 1) & 1) * (ATT_BUF_WORDS * 4));
            CP_WAIT(1);
        } else {
            CP_WAIT(0);
        }
        __syncthreads();

#pragma unroll
        for (int ks = 0; ks < 2; ks++) {
            const uint32_t kb = (uint32_t)(ks * 8) * 4;
            uint32_t ah[4], al[4];
            ldsm_x4(ah, bufb + aoff_h + kb);
            ldsm_x4(al, bufb + aoff_l + kb);
            // pass 1: bh (hh + lh), same-acc distance 2
#pragma unroll
            for (int p = 0; p < 8; p++) {
                uint32_t bh[4];
                ldsm_x4(bh, bufb + boff_h + (uint32_t)(p * 16 * 20) * 4 + kb);
                mma16816(acc[2 * p],     ah, bh[0], bh[1]);
                mma16816(acc[2 * p + 1], ah, bh[2], bh[3]);
                mma16816(acc[2 * p],     al, bh[0], bh[1]);
                mma16816(acc[2 * p + 1], al, bh[2], bh[3]);
            }
            // pass 2: bl (hl)
#pragma unroll
            for (int p = 0; p < 8; p++) {
                uint32_t bl[4];
                ldsm_x4(bl, bufb + boff_l + (uint32_t)(p * 16 * 20) * 4 + kb);
                mma16816(acc[2 * p],     ah, bl[0], bl[1]);
                mma16816(acc[2 * p + 1], ah, bl[2], bl[3]);
            }
        }
        __syncthreads();
    }

    // ---- epilogue: y2 from global (__ldg), P from smem ----
    const int r0 = m0w + g, r1 = r0 + 8;
    const int b0 = (m0 + r0) & 63, b1v = (m0 + r1) & 63;
    const float* y2p = g_y2 + (size_t)h * 64 * 256 + cx * 128;
    float ps0 = 0.f, ps1 = 0.f;
#pragma unroll
    for (int n8 = 0; n8 < 16; n8++) {
        const int cc0 = n8 * 8 + tg * 2;
        const float p0 = Ps[cc0], p1 = Ps[cc0 + 1];
        const float2 y0 = __ldg((const float2*)(y2p + b0 * 256 + cc0));
        const float2 y1 = __ldg((const float2*)(y2p + b1v * 256 + cc0));
        ps0 += tanhf(acc[n8][0] + y0.x) * p0 + tanhf(acc[n8][1] + y0.y) * p1;
        ps1 += tanhf(acc[n8][2] + y1.x) * p0 + tanhf(acc[n8][3] + y1.y) * p1;
    }
    ps0 += __shfl_xor_sync(0xffffffffu, ps0, 1);
    ps0 += __shfl_xor_sync(0xffffffffu, ps0, 2);
    ps1 += __shfl_xor_sync(0xffffffffu, ps1, 1);
    ps1 += __shfl_xor_sync(0xffffffffu, ps1, 2);
    if (tg == 0) {
        float* dst = g_attsp + (size_t)cx * (NHEAD * BATCH * SEQ);
        const int R0 = m0 + r0, R1 = m0 + r1;
        dst[((size_t)h * 64 + (R0 & 63)) * 512 + (R0 >> 6)] = ps0;
        dst[((size_t)h * 64 + (R1 & 63)) * 512 + (R1 >> 6)] = ps1;
    }
}

// ===========================================================================
// Row softmax over S=512, summing the two c-half partials. grid 512, blk 256.
// ===========================================================================
__global__ void k_softmax() {
    __shared__ float red[256];
    int row = blockIdx.x, tid = threadIdx.x;
    const float* a0 = g_attsp + (size_t)row * 512;
    const float* a1 = a0 + (size_t)NHEAD * BATCH * SEQ;
    float v0 = a0[tid] + a1[tid];
    float v1 = a0[tid + 256] + a1[tid + 256];
    red[tid] = fmaxf(v0, v1);
    __syncthreads();
    for (int o = 128; o > 0; o >>= 1) {
        if (tid < o) red[tid] = fmaxf(red[tid], red[tid + o]);
        __syncthreads();
    }
    float m = red[0];
    __syncthreads();
    float e0 = expf(v0 - m), e1 = expf(v1 - m);
    red[tid] = e0 + e1;
    __syncthreads();
    for (int o = 128; o > 0; o >>= 1) {
        if (tid < o) red[tid] += red[tid + o];
        __syncthreads();
    }
    float inv = 1.f / red[0];
    g_scores[(size_t)row * 512 + tid]       = e0 * inv;
    g_scores[(size_t)row * 512 + tid + 256] = e1 * inv;
}

// ===========================================================================
// Partial vs over s-chunks. grid (BATCH, 8), block 256.
// ===========================================================================
__global__ void __launch_bounds__(256)
k_out1() {
    __shared__ float sc[512];
    int b = blockIdx.x, sb = blockIdx.y, tid = threadIdx.x;
    for (int i = tid; i < 512; i += 256) {
        int h = i >> 6, ss = i & 63;
        sc[i] = g_scores[((size_t)h * 64 + b) * 512 + sb * 64 + ss];
    }
    __syncthreads();
    float acc[NHEAD] = {0.f, 0.f, 0.f, 0.f, 0.f, 0.f, 0.f, 0.f};
    const float* tvb = g_tv + ((size_t)b * 512 + sb * 64) * 256 + tid;
#pragma unroll 8
    for (int ss = 0; ss < 64; ss++) {
        float t = tvb[(size_t)ss * 256];
#pragma unroll
        for (int h = 0; h < NHEAD; h++) acc[h] = fmaf(sc[h * 64 + ss], t, acc[h]);
    }
#pragma unroll
    for (int h = 0; h < NHEAD; h++)
        g_vsp[((size_t)sb * 64 + b) * 2048 + h * 256 + tid] = acc[h];
}

// ===========================================================================
// Reduce partials + final cc. grid 64, block 128.
// ===========================================================================
__global__ void __launch_bounds__(128)
k_out2(const float* __restrict__ wcc, const float* __restrict__ bcc,
       float* __restrict__ out) {
    __shared__ float vsf[2048];
    int b = blockIdx.x, tid = threadIdx.x;
    for (int i = tid; i < 2048; i += 128) {
        float v = 0.f;
#pragma unroll
        for (int sb = 0; sb < 8; sb++)
            v += g_vsp[((size_t)sb * 64 + b) * 2048 + i];
        vsf[i] = v;
    }
    __syncthreads();
    float o = bcc[tid];
#pragma unroll 8
    for (int i = 0; i < 2048; i++) o = fmaf(vsf[i], wcc[i * 128 + tid], o);
    out[b * 128 + tid] = fmaxf(o, 0.f);
}

// ===========================================================================
extern "C" void kernel_launch(void* const* d_in, const int* in_sizes, int n_in,
                              void* d_out, int out_size) {
    const float* d1  = (const float*)d_in[0];
    const float* d2  = (const float*)d_in[1];
    const float* w1  = (const float*)d_in[2];
    const float* b1  = (const float*)d_in[3];
    const float* W   = (const float*)d_in[4];
    const float* P   = (const float*)d_in[5];
    const float* wv  = (const float*)d_in[6];
    const float* wcc = (const float*)d_in[7];
    const float* bcc = (const float*)d_in[8];
    float* out = (float*)d_out;

    cudaFuncSetAttribute(k_att_mma, cudaFuncAttributeMaxDynamicSharedMemorySize,
                         ATT_SMEM_BYTES);
    cudaFuncSetAttribute(k_proj_mma, cudaFuncAttributeMaxDynamicSharedMemorySize,
                         PROJ_SMEM_BYTES);

    k_d4<<<BATCH, COMP>>>(d1, w1, b1);
    k_y2<<<NHEAD, 256>>>(W);
    k_wsplit<<<10, 256>>>(W, w1, wv);
    k_proj_mma<<<dim3(2, 2, 256), 256, PROJ_SMEM_BYTES>>>(d2, b1);
    k_att_mma<<<dim3(2, NHEAD, SEQ / 2), 256, ATT_SMEM_BYTES>>>(P);
    k_softmax<<<NHEAD * BATCH, 256>>>();
    k_out1<<<dim3(BATCH, 8), 256>>>();
    k_out2<<<BATCH, 128>>>(wcc, bcc, out);
}

// round 14
// speedup vs baseline: 1.0294x; 1.0171x over previous
#include <cuda_runtime.h>
#include <cuda_bf16.h>
#include <cstdint>

#define SEQ   512
#define BATCH 64
#define FEAT  512
#define COMP  256
#define NHEAD 8

// Scratch (allocation-free rule: __device__ globals)
__device__ uint32_t g_d3p[(size_t)SEQ * BATCH * 256];   // d3 bf16 split: [row][128 hi | 128 lo] words
__device__ float g_tv[(size_t)BATCH * SEQ * COMP];      // [64][512][256]
__device__ float g_d4[BATCH * COMP];                    // [64][256]
__device__ float g_y2[NHEAD * BATCH * COMP];            // [8][64][256]
__device__ float g_attsp[2 * NHEAD * BATCH * SEQ];      // two c-half partials
__device__ float g_scores[NHEAD * BATCH * SEQ];
__device__ float g_vsp[16 * BATCH * NHEAD * COMP];      // [16 sb][64][2048]
// W^T bf16 split for k_att: [h][c][k<256]
__device__ __align__(16) __nv_bfloat16 g_Wth[NHEAD * 256 * 256];
__device__ __align__(16) __nv_bfloat16 g_Wtl[NHEAD * 256 * 256];
// w1/wv transposed split for k_proj: [path][c][k<512]
__device__ __align__(16) __nv_bfloat16 g_wpth[2 * 256 * 512];
__device__ __align__(16) __nv_bfloat16 g_wptl[2 * 256 * 512];

__device__ __forceinline__ uint32_t smem_u32(const void* p) {
    uint32_t a;
    asm("{ .reg .u64 t; cvta.to.shared.u64 t, %1; cvt.u32.u64 %0, t; }" : "=r"(a) : "l"(p));
    return a;
}

#define CP16(dst, src) \
    asm volatile("cp.async.ca.shared.global [%0], [%1], 16;" :: "r"(dst), "l"(src) : "memory")
#define CP_COMMIT() asm volatile("cp.async.commit_group;" ::: "memory")
#define CP_WAIT(n)  asm volatile("cp.async.wait_group %0;" :: "n"(n) : "memory")

// fast tanh: abs error ~1e-7, clamped (tanh(12) == 1.0f in fp32)
__device__ __forceinline__ float ftanh(float x) {
    float ax = fminf(fabsf(x), 12.0f);
    float e  = __expf(2.0f * ax);
    float t  = __fdividef(e - 1.0f, e + 1.0f);
    return copysignf(t, x);
}

// bf16 split of a pair of floats -> packed hi and lo words (packed cvt)
__device__ __forceinline__ void split2(float a, float b, uint32_t& hi, uint32_t& lo) {
    __nv_bfloat162 h2 = __float22bfloat162_rn(make_float2(a, b));
    float2 back = __bfloat1622float2(h2);
    __nv_bfloat162 l2 = __float22bfloat162_rn(make_float2(a - back.x, b - back.y));
    hi = *reinterpret_cast<uint32_t*>(&h2);
    lo = *reinterpret_cast<uint32_t*>(&l2);
}

__device__ __forceinline__ void mma16816(float c[4], const uint32_t a[4],
                                         uint32_t b0, uint32_t b1) {
    asm volatile(
        "mma.sync.aligned.m16n8k16.row.col.f32.bf16.bf16.f32 "
        "{%0,%1,%2,%3}, {%4,%5,%6,%7}, {%8,%9}, {%0,%1,%2,%3};"
        : "+f"(c[0]), "+f"(c[1]), "+f"(c[2]), "+f"(c[3])
        : "r"(a[0]), "r"(a[1]), "r"(a[2]), "r"(a[3]), "r"(b0), "r"(b1));
}

__device__ __forceinline__ void ldsm_x4(uint32_t r[4], uint32_t addr) {
    asm volatile("ldmatrix.sync.aligned.m8n8.x4.shared.b16 {%0,%1,%2,%3}, [%4];"
        : "=r"(r[0]), "=r"(r[1]), "=r"(r[2]), "=r"(r[3]) : "r"(addr));
}

// ===========================================================================
// d4 = relu(d1 @ w1 + b1)   [64,256]
// ===========================================================================
__global__ void k_d4(const float* __restrict__ d1, const float* __restrict__ w1,
                     const float* __restrict__ b1) {
    __shared__ float row[FEAT];
    int b = blockIdx.x, c = threadIdx.x;
    for (int i = c; i < FEAT; i += blockDim.x) row[i] = d1[b * FEAT + i];
    __syncthreads();
    float acc = b1[c];
#pragma unroll 8
    for (int d = 0; d < FEAT; d++) acc = fmaf(row[d], w1[d * COMP + c], acc);
    g_d4[b * COMP + c] = fmaxf(acc, 0.f);
}

// ===========================================================================
// 64-row fp32 tile GEMM (round-2 proven). 256 threads, 8x8 microtile.
// ===========================================================================
template <int K, int LDA>
__device__ __forceinline__ void gemm_tile64(const float* __restrict__ A,
                                            const float* __restrict__ Bm,
                                            float acc[8][8]) {
    __shared__ float As[16 * 64];
    __shared__ float Bs[16 * 256];
    int tid  = threadIdx.x;
    int am   = tid >> 2;
    int ak   = (tid & 3) << 2;
    int bn   = (tid & 63) << 2;
    int bk   = (tid >> 6) << 2;
    int rowb = (tid >> 5) << 3;
    int cb   = (tid & 31) << 2;

#pragma unroll
    for (int i = 0; i < 8; i++)
#pragma unroll
        for (int j = 0; j < 8; j++) acc[i][j] = 0.f;

    for (int k0 = 0; k0 < K; k0 += 16) {
        float4 av = *(const float4*)(A + am * LDA + k0 + ak);
        As[(ak + 0) * 64 + am] = av.x;
        As[(ak + 1) * 64 + am] = av.y;
        As[(ak + 2) * 64 + am] = av.z;
        As[(ak + 3) * 64 + am] = av.w;
#pragma unroll
        for (int i = 0; i < 4; i++) {
            *(float4*)(Bs + (bk + i) * 256 + bn) =
                *(const float4*)(Bm + (size_t)(k0 + bk + i) * 256 + bn);
        }
        __syncthreads();
#pragma unroll
        for (int kk = 0; kk < 16; kk++) {
            float4 a0 = *(const float4*)(As + kk * 64 + rowb);
            float4 a1 = *(const float4*)(As + kk * 64 + rowb + 4);
            float4 b0 = *(const float4*)(Bs + kk * 256 + cb);
            float4 b1 = *(const float4*)(Bs + kk * 256 + cb + 128);
            float a[8]  = {a0.x, a0.y, a0.z, a0.w, a1.x, a1.y, a1.z, a1.w};
            float bb[8] = {b0.x, b0.y, b0.z, b0.w, b1.x, b1.y, b1.z, b1.w};
#pragma unroll
            for (int i = 0; i < 8; i++)
#pragma unroll
                for (int j = 0; j < 8; j++)
                    acc[i][j] = fmaf(a[i], bb[j], acc[i][j]);
        }
        __syncthreads();
    }
}

// ===========================================================================
// y2[h][b][c] = d4[b,:] @ W_h[256:512,:]   grid NHEAD, block 256.
// ===========================================================================
__global__ void __launch_bounds__(256)
k_y2(const float* __restrict__ W) {
    int h = blockIdx.x;
    float acc[8][8];
    gemm_tile64<COMP, COMP>(g_d4, W + (size_t)h * 512 * 256 + 256 * 256, acc);
    int tid  = threadIdx.x;
    int rowb = (tid >> 5) << 3;
    int cb   = (tid & 31) << 2;
#pragma unroll
    for (int i = 0; i < 8; i++)
#pragma unroll
        for (int j = 0; j < 8; j++) {
            int c = (j < 4) ? cb + j : cb + 124 + j;
            g_y2[((size_t)h * 64 + rowb + i) * 256 + c] = acc[i][j];
        }
}

// ===========================================================================
// Weight split prep (fused): blocks 0..7 -> W^T split (k_att);
// blocks 8..9 -> w1/wv transposed split (k_proj). grid 10, block 256.
// ===========================================================================
__global__ void __launch_bounds__(256)
k_wsplit(const float* __restrict__ W, const float* __restrict__ w1,
         const float* __restrict__ wv) {
    if (blockIdx.x < 8) {
        int h = blockIdx.x;
        for (int i = threadIdx.x; i < 256 * 256; i += 256) {
            int k = i >> 8, c = i & 255;
            float v = W[((size_t)h * 512 + k) * 256 + c];
            __nv_bfloat16 hi = __float2bfloat16_rn(v);
            __nv_bfloat16 lo = __float2bfloat16_rn(v - __bfloat162float(hi));
            size_t o = ((size_t)h * 256 + c) * 256 + k;
            g_Wth[o] = hi;
            g_Wtl[o] = lo;
        }
    } else {
        int path = blockIdx.x - 8;
        const float* w = path ? wv : w1;
        for (int i = threadIdx.x; i < 256 * 512; i += 256) {
            int c = i >> 9, k = i & 511;
            float v = w[(size_t)k * 256 + c];
            __nv_bfloat16 hi = __float2bfloat16_rn(v);
            __nv_bfloat16 lo = __float2bfloat16_rn(v - __bfloat162float(hi));
            size_t o = ((size_t)path * 256 + c) * 512 + k;
            g_wpth[o] = hi;
            g_wptl[o] = lo;
        }
    }
}

// ===========================================================================
// k_proj via HMMA bf16-split + ldmatrix (round-13 ordering).
// grid (2 cx, 2 path, 256 mblk), blk 256. 16x128 warp tile.
// Smem words: Ah 0, Al 4608, Bh 9216, Bl 13824 (pitch 36), b1s 18432.
// ===========================================================================
#define PROJ_SMEM_WORDS 18560
#define PROJ_SMEM_BYTES (PROJ_SMEM_WORDS * 4)

__global__ void __launch_bounds__(256, 2)
k_proj_mma(const float* __restrict__ d2, const float* __restrict__ b1) {
    extern __shared__ __align__(16) uint32_t sm[];
    uint32_t* Ah = sm;
    uint32_t* Al = sm + 4608;
    uint32_t* Bh = sm + 9216;
    uint32_t* Bl = sm + 13824;
    float*    b1s = (float*)(sm + 18432);

    const int cx = blockIdx.x, path = blockIdx.y, zb = blockIdx.z;
    const int m0 = zb * 128;
    const int tid = threadIdx.x;
    const int wid = tid >> 5;
    const int lane = tid & 31;
    const int g  = lane >> 2;
    const int tg = lane & 3;
    const int m0w = wid * 16;

    if (path == 0 && tid < 128) b1s[tid] = b1[cx * 128 + tid];

    const uint32_t smb = smem_u32(sm);
    const int arow = m0w + (lane & 7) + ((lane >> 3) & 1) * 8;
    const int akoff = (lane >> 4) * 4;
    const uint32_t aaddr_h = smb + (uint32_t)(arow * 36 + akoff) * 4;
    const uint32_t aaddr_l = aaddr_h + 4608u * 4;
    const int brow = (lane & 7) + ((lane >> 4) << 3);
    const int bkoff = ((lane >> 3) & 1) * 4;
    const uint32_t baddr_h = smb + (uint32_t)(9216 + brow * 36 + bkoff) * 4;
    const uint32_t baddr_l = baddr_h + 4608u * 4;

    float acc[16][4];
#pragma unroll
    for (int n8 = 0; n8 < 16; n8++)
#pragma unroll
        for (int e = 0; e < 4; e++) acc[n8][e] = 0.f;

    const __nv_bfloat16* Wh = g_wpth + ((size_t)path * 256 + cx * 128) * 512;
    const __nv_bfloat16* Wl = g_wptl + ((size_t)path * 256 + cx * 128) * 512;

    for (int ch = 0; ch < 8; ch++) {
        __syncthreads();
        for (int t = tid; t < 2048; t += 256) {
            int r = t >> 4, j = t & 15;
            float4 v = *(const float4*)(d2 + (size_t)(m0 + r) * 512 + ch * 64 + j * 4);
            uint32_t hi0, lo0, hi1, lo1;
            split2(v.x, v.y, hi0, lo0);
            split2(v.z, v.w, hi1, lo1);
            Ah[r * 36 + j * 2]     = hi0;
            Ah[r * 36 + j * 2 + 1] = hi1;
            Al[r * 36 + j * 2]     = lo0;
            Al[r * 36 + j * 2 + 1] = lo1;
        }
        for (int t = tid; t < 2048; t += 256) {
            int n = t >> 4, j = t & 15;
            int plane = j >> 3, j8 = j & 7;
            const uint4* srow = (const uint4*)((plane ? Wl : Wh) + (size_t)n * 512 + ch * 64);
            uint32_t* dstp = (plane ? Bl : Bh) + n * 36 + j8 * 4;
            *(uint4*)dstp = srow[j8];
        }
        __syncthreads();

#pragma unroll
        for (int ks = 0; ks < 4; ks++) {
            const uint32_t kb = (uint32_t)(ks * 8) * 4;
            uint32_t ah[4], al[4];
            ldsm_x4(ah, aaddr_h + kb);
            ldsm_x4(al, aaddr_l + kb);
#pragma unroll
            for (int p = 0; p < 8; p++) {
                uint32_t bh[4];
                ldsm_x4(bh, baddr_h + (uint32_t)(p * 16 * 36) * 4 + kb);
                mma16816(acc[2 * p],     ah, bh[0], bh[1]);
                mma16816(acc[2 * p + 1], ah, bh[2], bh[3]);
                mma16816(acc[2 * p],     al, bh[0], bh[1]);
                mma16816(acc[2 * p + 1], al, bh[2], bh[3]);
            }
#pragma unroll
            for (int p = 0; p < 8; p++) {
                uint32_t bl[4];
                ldsm_x4(bl, baddr_l + (uint32_t)(p * 16 * 36) * 4 + kb);
                mma16816(acc[2 * p],     ah, bl[0], bl[1]);
                mma16816(acc[2 * p + 1], ah, bl[2], bl[3]);
            }
        }
    }

    const int r0 = m0w + g, r1 = r0 + 8;
    const int R0 = m0 + r0, R1 = m0 + r1;
    if (path == 0) {
        uint32_t* dst0 = g_d3p + (size_t)R0 * 256;
        uint32_t* dst1 = g_d3p + (size_t)R1 * 256;
#pragma unroll
        for (int n8 = 0; n8 < 16; n8++) {
            const int cc = n8 * 8 + tg * 2;
            const int word = cx * 64 + n8 * 4 + tg;
            const float bb0 = b1s[cc], bb1 = b1s[cc + 1];
            uint32_t hi, lo;
            float v0 = fmaxf(acc[n8][0] + bb0, 0.f);
            float v1 = fmaxf(acc[n8][1] + bb1, 0.f);
            split2(v0, v1, hi, lo);
            dst0[word] = hi; dst0[128 + word] = lo;
            float v2 = fmaxf(acc[n8][2] + bb0, 0.f);
            float v3 = fmaxf(acc[n8][3] + bb1, 0.f);
            split2(v2, v3, hi, lo);
            dst1[word] = hi; dst1[128 + word] = lo;
        }
    } else {
        const int s0 = R0 >> 6, b0i = R0 & 63;
        const int s1 = R1 >> 6, b1i = R1 & 63;
        float* t0 = g_tv + ((size_t)b0i * 512 + s0) * 256 + cx * 128;
        float* t1 = g_tv + ((size_t)b1i * 512 + s1) * 256 + cx * 128;
#pragma unroll
        for (int n8 = 0; n8 < 16; n8++) {
            const int cc = n8 * 8 + tg * 2;
            *(float2*)(t0 + cc) = make_float2(ftanh(acc[n8][0]), ftanh(acc[n8][1]));
            *(float2*)(t1 + cc) = make_float2(ftanh(acc[n8][2]), ftanh(acc[n8][3]));
        }
    }
}

// ===========================================================================
// k_att via HMMA + cp.async 2-stage pipeline, strength-reduced issue.
// grid (2 cx, 8 h, 256), blk 256. k=32 chunks (8), double-buffered.
// Buf layout (words, pitch 20): Ah [0,2560) Al [2560,5120) Bh [5120,7680)
// Bl [7680,10240); buf1 at 10240. Ps at word 20480.
// ===========================================================================
#define ATT_BUF_WORDS 10240
#define ATT_SMEM_WORDS (2 * ATT_BUF_WORDS + 128)
#define ATT_SMEM_BYTES (ATT_SMEM_WORDS * 4)

__global__ void __launch_bounds__(256, 2)
k_att_mma(const float* __restrict__ P) {
    extern __shared__ __align__(16) uint32_t sm[];
    float* Ps = (float*)(sm + 2 * ATT_BUF_WORDS);

    const int cx = blockIdx.x, h = blockIdx.y, zb = blockIdx.z;
    const int m0 = zb * 128;
    const int tid = threadIdx.x;
    const int wid = tid >> 5;
    const int lane = tid & 31;
    const int g  = lane >> 2;
    const int tg = lane & 3;
    const int m0w = wid * 16;

    if (tid < 128) Ps[tid] = P[h * 256 + cx * 128 + tid];

    const uint32_t smb = smem_u32(sm);
    const int arow = m0w + (lane & 7) + ((lane >> 3) & 1) * 8;
    const int akoff = (lane >> 4) * 4;
    const uint32_t aoff_h = (uint32_t)(arow * 20 + akoff) * 4;
    const uint32_t aoff_l = aoff_h + 2560u * 4;
    const int brow = (lane & 7) + ((lane >> 4) << 3);
    const int bkoff = ((lane >> 3) & 1) * 4;
    const uint32_t boff_h = (uint32_t)(5120 + brow * 20 + bkoff) * 4;
    const uint32_t boff_l = boff_h + 2560u * 4;

    const __nv_bfloat16* Wh = g_Wth + ((size_t)h * 256 + cx * 128) * 256;
    const __nv_bfloat16* Wl = g_Wtl + ((size_t)h * 256 + cx * 128) * 256;

    // strength-reduced cp.async decomposition: decode (r0, plane, w4) once.
    // t = tid + 256*i  ->  row = (tid>>3) + 32*i, j = tid&7 invariant.
    const uint32_t cr0 = tid >> 3;          // 0..31
    const int jj  = tid & 7;
    const int pl  = jj >> 2;                // 0 hi, 1 lo
    const int w4  = (jj & 3) * 4;           // word offset
    const uint32_t* srcA0 = g_d3p + (size_t)(m0 + cr0) * 256 + pl * 128 + w4;
    const __nv_bfloat16* srcB0 = (pl ? Wl : Wh) + (size_t)cr0 * 256 + w4 * 2;
    const uint32_t dstA0 = (uint32_t)((pl ? 2560 : 0) + cr0 * 20 + w4) * 4;
    const uint32_t dstB0 = (uint32_t)((pl ? 7680 : 5120) + cr0 * 20 + w4) * 4;

    float acc[16][4];
#pragma unroll
    for (int n8 = 0; n8 < 16; n8++)
#pragma unroll
        for (int e = 0; e < 4; e++) acc[n8][e] = 0.f;

    auto issue = [&](int ch, uint32_t dstb) {
        const uint32_t* sa = srcA0 + ch * 16;
        const __nv_bfloat16* sb = srcB0 + ch * 32;
#pragma unroll
        for (int i = 0; i < 4; i++)
            CP16(dstb + dstA0 + (uint32_t)i * (32 * 20 * 4), sa + (size_t)i * (32 * 256));
#pragma unroll
        for (int i = 0; i < 4; i++)
            CP16(dstb + dstB0 + (uint32_t)i * (32 * 20 * 4), sb + (size_t)i * (32 * 256));
        CP_COMMIT();
    };

    issue(0, smb);

    for (int ch = 0; ch < 8; ch++) {
        const uint32_t bufb = smb + (uint32_t)(ch & 1) * (ATT_BUF_WORDS * 4);
        if (ch + 1 < 8) {
            issue(ch + 1, smb + (uint32_t)((ch + 1) & 1) * (ATT_BUF_WORDS * 4));
            CP_WAIT(1);
        } else {
            CP_WAIT(0);
        }
        __syncthreads();

#pragma unroll
        for (int ks = 0; ks < 2; ks++) {
            const uint32_t kb = (uint32_t)(ks * 8) * 4;
            uint32_t ah[4], al[4];
            ldsm_x4(ah, bufb + aoff_h + kb);
            ldsm_x4(al, bufb + aoff_l + kb);
#pragma unroll
            for (int p = 0; p < 8; p++) {
                uint32_t bh[4];
                ldsm_x4(bh, bufb + boff_h + (uint32_t)(p * 16 * 20) * 4 + kb);
                mma16816(acc[2 * p],     ah, bh[0], bh[1]);
                mma16816(acc[2 * p + 1], ah, bh[2], bh[3]);
                mma16816(acc[2 * p],     al, bh[0], bh[1]);
                mma16816(acc[2 * p + 1], al, bh[2], bh[3]);
            }
#pragma unroll
            for (int p = 0; p < 8; p++) {
                uint32_t bl[4];
                ldsm_x4(bl, bufb + boff_l + (uint32_t)(p * 16 * 20) * 4 + kb);
                mma16816(acc[2 * p],     ah, bl[0], bl[1]);
                mma16816(acc[2 * p + 1], ah, bl[2], bl[3]);
            }
        }
        __syncthreads();
    }

    // ---- epilogue: y2 from global (__ldg), P from smem ----
    const int r0 = m0w + g, r1 = r0 + 8;
    const int b0 = (m0 + r0) & 63, b1v = (m0 + r1) & 63;
    const float* y2p = g_y2 + (size_t)h * 64 * 256 + cx * 128;
    float ps0 = 0.f, ps1 = 0.f;
#pragma unroll
    for (int n8 = 0; n8 < 16; n8++) {
        const int cc0 = n8 * 8 + tg * 2;
        const float p0 = Ps[cc0], p1 = Ps[cc0 + 1];
        const float2 y0 = __ldg((const float2*)(y2p + b0 * 256 + cc0));
        const float2 y1 = __ldg((const float2*)(y2p + b1v * 256 + cc0));
        ps0 += ftanh(acc[n8][0] + y0.x) * p0 + ftanh(acc[n8][1] + y0.y) * p1;
        ps1 += ftanh(acc[n8][2] + y1.x) * p0 + ftanh(acc[n8][3] + y1.y) * p1;
    }
    ps0 += __shfl_xor_sync(0xffffffffu, ps0, 1);
    ps0 += __shfl_xor_sync(0xffffffffu, ps0, 2);
    ps1 += __shfl_xor_sync(0xffffffffu, ps1, 1);
    ps1 += __shfl_xor_sync(0xffffffffu, ps1, 2);
    if (tg == 0) {
        float* dst = g_attsp + (size_t)cx * (NHEAD * BATCH * SEQ);
        const int R0 = m0 + r0, R1 = m0 + r1;
        dst[((size_t)h * 64 + (R0 & 63)) * 512 + (R0 >> 6)] = ps0;
        dst[((size_t)h * 64 + (R1 & 63)) * 512 + (R1 >> 6)] = ps1;
    }
}

// ===========================================================================
// Row softmax over S=512, summing the two c-half partials. grid 512, blk 256.
// ===========================================================================
__global__ void k_softmax() {
    __shared__ float red[256];
    int row = blockIdx.x, tid = threadIdx.x;
    const float* a0 = g_attsp + (size_t)row * 512;
    const float* a1 = a0 + (size_t)NHEAD * BATCH * SEQ;
    float v0 = a0[tid] + a1[tid];
    float v1 = a0[tid + 256] + a1[tid + 256];
    red[tid] = fmaxf(v0, v1);
    __syncthreads();
    for (int o = 128; o > 0; o >>= 1) {
        if (tid < o) red[tid] = fmaxf(red[tid], red[tid + o]);
        __syncthreads();
    }
    float m = red[0];
    __syncthreads();
    float e0 = expf(v0 - m), e1 = expf(v1 - m);
    red[tid] = e0 + e1;
    __syncthreads();
    for (int o = 128; o > 0; o >>= 1) {
        if (tid < o) red[tid] += red[tid + o];
        __syncthreads();
    }
    float inv = 1.f / red[0];
    g_scores[(size_t)row * 512 + tid]       = e0 * inv;
    g_scores[(size_t)row * 512 + tid + 256] = e1 * inv;
}

// ===========================================================================
// Partial vs over s-chunks. grid (BATCH, 16), block 256.
// ===========================================================================
__global__ void __launch_bounds__(256)
k_out1() {
    __shared__ float sc[256];   // [h][32]
    int b = blockIdx.x, sb = blockIdx.y, tid = threadIdx.x;
    {
        int hh = tid >> 5, ss = tid & 31;
        sc[tid] = g_scores[((size_t)hh * 64 + b) * 512 + sb * 32 + ss];
    }
    __syncthreads();
    float acc[NHEAD] = {0.f, 0.f, 0.f, 0.f, 0.f, 0.f, 0.f, 0.f};
    const float* tvb = g_tv + ((size_t)b * 512 + sb * 32) * 256 + tid;
#pragma unroll 8
    for (int ss = 0; ss < 32; ss++) {
        float t = tvb[(size_t)ss * 256];
#pragma unroll
        for (int h = 0; h < NHEAD; h++) acc[h] = fmaf(sc[h * 32 + ss], t, acc[h]);
    }
#pragma unroll
    for (int h = 0; h < NHEAD; h++)
        g_vsp[((size_t)sb * 64 + b) * 2048 + h * 256 + tid] = acc[h];
}

// ===========================================================================
// Reduce partials + final cc. grid 64, block 128.
// ===========================================================================
__global__ void __launch_bounds__(128)
k_out2(const float* __restrict__ wcc, const float* __restrict__ bcc,
       float* __restrict__ out) {
    __shared__ float vsf[2048];
    int b = blockIdx.x, tid = threadIdx.x;
    for (int i = tid; i < 2048; i += 128) {
        float v = 0.f;
#pragma unroll
        for (int sb = 0; sb < 16; sb++)
            v += g_vsp[((size_t)sb * 64 + b) * 2048 + i];
        vsf[i] = v;
    }
    __syncthreads();
    float o = bcc[tid];
#pragma unroll 8
    for (int i = 0; i < 2048; i++) o = fmaf(vsf[i], wcc[i * 128 + tid], o);
    out[b * 128 + tid] = fmaxf(o, 0.f);
}

// ===========================================================================
extern "C" void kernel_launch(void* const* d_in, const int* in_sizes, int n_in,
                              void* d_out, int out_size) {
    const float* d1  = (const float*)d_in[0];
    const float* d2  = (const float*)d_in[1];
    const float* w1  = (const float*)d_in[2];
    const float* b1  = (const float*)d_in[3];
    const float* W   = (const float*)d_in[4];
    const float* P   = (const float*)d_in[5];
    const float* wv  = (const float*)d_in[6];
    const float* wcc = (const float*)d_in[7];
    const float* bcc = (const float*)d_in[8];
    float* out = (float*)d_out;

    cudaFuncSetAttribute(k_att_mma, cudaFuncAttributeMaxDynamicSharedMemorySize,
                         ATT_SMEM_BYTES);
    cudaFuncSetAttribute(k_proj_mma, cudaFuncAttributeMaxDynamicSharedMemorySize,
                         PROJ_SMEM_BYTES);

    k_d4<<<BATCH, COMP>>>(d1, w1, b1);
    k_y2<<<NHEAD, 256>>>(W);
    k_wsplit<<<10, 256>>>(W, w1, wv);
    k_proj_mma<<<dim3(2, 2, 256), 256, PROJ_SMEM_BYTES>>>(d2, b1);
    k_att_mma<<<dim3(2, NHEAD, SEQ / 2), 256, ATT_SMEM_BYTES>>>(P);
    k_softmax<<<NHEAD * BATCH, 256>>>();
    k_out1<<<dim3(BATCH, 16), 256>>>();
    k_out2<<<BATCH, 128>>>(wcc, bcc, out);
}